// round 1
// baseline (speedup 1.0000x reference)
#include <cuda_runtime.h>
#include <cuda_bf16.h>

#define N_NODES 40000
#define DFEAT   128
#define N_EDGES 640000

// Scratch (static device globals — no allocation)
__device__ float g_h[N_NODES * DFEAT];   // h = ndata + mean(neighbors)
__device__ int   g_deg[N_NODES];
__device__ float g_inv[N_NODES];

// ---------------------------------------------------------------------------
// k_init: h = ndata (vectorized copy), deg = 0
// ---------------------------------------------------------------------------
__global__ void k_init(const float* __restrict__ ndata) {
    int i = blockIdx.x * blockDim.x + threadIdx.x;
    const int total4 = N_NODES * DFEAT / 4;   // 1,280,000 float4
    if (i < total4) {
        reinterpret_cast<float4*>(g_h)[i] =
            reinterpret_cast<const float4*>(ndata)[i];
    }
    if (i < N_NODES) g_deg[i] = 0;
}

// ---------------------------------------------------------------------------
// k_deg: in-degree histogram
// ---------------------------------------------------------------------------
__global__ void k_deg(const int* __restrict__ dst) {
    int e = blockIdx.x * blockDim.x + threadIdx.x;
    if (e < N_EDGES) atomicAdd(&g_deg[dst[e]], 1);
}

// ---------------------------------------------------------------------------
// k_inv: inv_deg = 1 / max(deg, 1)
// ---------------------------------------------------------------------------
__global__ void k_inv() {
    int v = blockIdx.x * blockDim.x + threadIdx.x;
    if (v < N_NODES) {
        int d = g_deg[v];
        g_inv[v] = 1.0f / (float)(d > 0 ? d : 1);
    }
}

// ---------------------------------------------------------------------------
// k_scatter: one warp per edge. lane handles 4 consecutive floats.
// h[dst] += ndata[src] * inv_deg[dst]   (atomic, RED.F32 no-return)
// ---------------------------------------------------------------------------
__global__ void k_scatter(const float* __restrict__ ndata,
                          const int* __restrict__ src,
                          const int* __restrict__ dst) {
    int gt   = blockIdx.x * blockDim.x + threadIdx.x;
    int e    = gt >> 5;
    int lane = gt & 31;
    if (e >= N_EDGES) return;

    int s = __ldg(src + e);
    int d = __ldg(dst + e);
    float inv = __ldg(&g_inv[d]);   // broadcast within warp via L1

    float4 x = __ldg(reinterpret_cast<const float4*>(ndata + (size_t)s * DFEAT) + lane);
    float* base = g_h + (size_t)d * DFEAT + lane * 4;
    atomicAdd(base + 0, x.x * inv);
    atomicAdd(base + 1, x.y * inv);
    atomicAdd(base + 2, x.z * inv);
    atomicAdd(base + 3, x.w * inv);
}

// ---------------------------------------------------------------------------
// k_gemm: out[M,128] = h[M,128] @ W[128,128]^T + b
// out[i][j] = sum_k h[i][k] * W[j][k] + b[j]
// BM=128, BN=128, BK=16, 256 threads, 8x8 microtile per thread.
// ---------------------------------------------------------------------------
__global__ __launch_bounds__(256) void k_gemm(const float* __restrict__ W,
                                              const float* __restrict__ b,
                                              float* __restrict__ out) {
    const int M = N_NODES;
    __shared__ float As[16][128];   // [k][m]
    __shared__ float Bs[16][128];   // [k][n]  (n = output col j; W[j][k])

    int tid = threadIdx.x;
    int blockRow = blockIdx.x * 128;
    int tr = tid >> 4;       // 0..15
    int tc = tid & 15;       // 0..15

    float acc[8][8];
#pragma unroll
    for (int i = 0; i < 8; i++)
#pragma unroll
        for (int j = 0; j < 8; j++) acc[i][j] = 0.0f;

#pragma unroll 1
    for (int k0 = 0; k0 < 128; k0 += 16) {
        // Load A tile (128 rows x 16 k) and B tile (128 cols x 16 k), transposed.
#pragma unroll
        for (int t = 0; t < 2; t++) {
            int idx = tid + t * 256;     // 0..511 (512 float4 per tile)
            int row = idx >> 2;          // 0..127
            int kq  = idx & 3;           // float4 index within BK=16

            int grow = blockRow + row;
            float4 v = make_float4(0.f, 0.f, 0.f, 0.f);
            if (grow < M)
                v = __ldg(reinterpret_cast<const float4*>(
                        g_h + (size_t)grow * 128 + k0) + kq);
            As[kq * 4 + 0][row] = v.x;
            As[kq * 4 + 1][row] = v.y;
            As[kq * 4 + 2][row] = v.z;
            As[kq * 4 + 3][row] = v.w;

            float4 w = __ldg(reinterpret_cast<const float4*>(
                    W + (size_t)row * 128 + k0) + kq);
            Bs[kq * 4 + 0][row] = w.x;
            Bs[kq * 4 + 1][row] = w.y;
            Bs[kq * 4 + 2][row] = w.z;
            Bs[kq * 4 + 3][row] = w.w;
        }
        __syncthreads();

#pragma unroll
        for (int k = 0; k < 16; k++) {
            float4 a0 = *reinterpret_cast<const float4*>(&As[k][tr * 8]);
            float4 a1 = *reinterpret_cast<const float4*>(&As[k][tr * 8 + 4]);
            float4 b0 = *reinterpret_cast<const float4*>(&Bs[k][tc * 8]);
            float4 b1 = *reinterpret_cast<const float4*>(&Bs[k][tc * 8 + 4]);
            float rm[8] = {a0.x, a0.y, a0.z, a0.w, a1.x, a1.y, a1.z, a1.w};
            float rn[8] = {b0.x, b0.y, b0.z, b0.w, b1.x, b1.y, b1.z, b1.w};
#pragma unroll
            for (int i = 0; i < 8; i++)
#pragma unroll
                for (int j = 0; j < 8; j++)
                    acc[i][j] += rm[i] * rn[j];
        }
        __syncthreads();
    }

    // Epilogue: add bias, write out (float4)
    float bias[8];
#pragma unroll
    for (int j = 0; j < 8; j++) bias[j] = __ldg(b + tc * 8 + j);

#pragma unroll
    for (int i = 0; i < 8; i++) {
        int grow = blockRow + tr * 8 + i;
        if (grow < M) {
            float4 o0, o1;
            o0.x = acc[i][0] + bias[0];
            o0.y = acc[i][1] + bias[1];
            o0.z = acc[i][2] + bias[2];
            o0.w = acc[i][3] + bias[3];
            o1.x = acc[i][4] + bias[4];
            o1.y = acc[i][5] + bias[5];
            o1.z = acc[i][6] + bias[6];
            o1.w = acc[i][7] + bias[7];
            float4* op = reinterpret_cast<float4*>(out + (size_t)grow * 128 + tc * 8);
            op[0] = o0;
            op[1] = o1;
        }
    }
}

// ---------------------------------------------------------------------------
extern "C" void kernel_launch(void* const* d_in, const int* in_sizes, int n_in,
                              void* d_out, int out_size) {
    const float* ndata = (const float*)d_in[0];
    const int*   src   = (const int*)d_in[1];
    const int*   dst   = (const int*)d_in[2];
    const float* W     = (const float*)d_in[3];
    const float* b     = (const float*)d_in[4];
    float* out = (float*)d_out;

    (void)in_sizes; (void)n_in; (void)out_size;

    // init h = ndata, deg = 0
    {
        int total4 = N_NODES * DFEAT / 4;
        k_init<<<(total4 + 255) / 256, 256>>>(ndata);
    }
    // degree histogram
    k_deg<<<(N_EDGES + 255) / 256, 256>>>(dst);
    // inverse degree
    k_inv<<<(N_NODES + 255) / 256, 256>>>();
    // scatter: one warp per edge
    {
        long long threads = (long long)N_EDGES * 32;
        int blocks = (int)((threads + 255) / 256);
        k_scatter<<<blocks, 256>>>(ndata, src, dst);
    }
    // GEMM + bias
    {
        int blocks = (N_NODES + 127) / 128;
        k_gemm<<<blocks, 256>>>(W, b, out);
    }
}

// round 3
// speedup vs baseline: 1.6802x; 1.6802x over previous
#include <cuda_runtime.h>
#include <cuda_bf16.h>

#define N_NODES 40000
#define DFEAT   128
#define N_EDGES 640000

// Scratch (static device globals — no allocation)
__device__ float g_h[N_NODES * DFEAT];    // h = ndata + mean(neighbors)
__device__ int   g_deg[N_NODES];
__device__ int   g_off[N_NODES + 1];      // CSR row offsets
__device__ int   g_cur[N_NODES];          // fill cursors
__device__ int   g_csrc[N_EDGES];         // CSR-ordered source indices

// ---------------------------------------------------------------------------
// k_zero: deg = 0
// ---------------------------------------------------------------------------
__global__ void k_zero() {
    int i = blockIdx.x * blockDim.x + threadIdx.x;
    if (i < N_NODES) g_deg[i] = 0;
}

// ---------------------------------------------------------------------------
// k_deg: in-degree histogram (int atomics — cheap)
// ---------------------------------------------------------------------------
__global__ void k_deg(const int* __restrict__ dst) {
    int e = blockIdx.x * blockDim.x + threadIdx.x;
    if (e < N_EDGES) atomicAdd(&g_deg[dst[e]], 1);
}

// ---------------------------------------------------------------------------
// k_scan: single-block exclusive scan over 40000 degrees.
// 1024 threads, each owns a 40-element contiguous chunk.
// ---------------------------------------------------------------------------
__global__ __launch_bounds__(1024) void k_scan() {
    const int CHUNK = 40;          // 1024 * 40 = 40960 >= 40000
    __shared__ int partial[1024];
    int tid = threadIdx.x;
    int base = tid * CHUNK;

    int local[CHUNK];
    int sum = 0;
#pragma unroll
    for (int j = 0; j < CHUNK; j++) {
        int idx = base + j;
        int d = (idx < N_NODES) ? g_deg[idx] : 0;
        local[j] = d;
        sum += d;
    }
    partial[tid] = sum;
    __syncthreads();

    // Hillis-Steele inclusive scan in shared (1024 elems, 10 steps)
    int val = sum;
    for (int s = 1; s < 1024; s <<= 1) {
        int other = (tid >= s) ? partial[tid - s] : 0;
        __syncthreads();
        val += other;
        partial[tid] = val;
        __syncthreads();
    }
    int excl = val - sum;   // exclusive prefix of this thread's chunk

    int running = excl;
#pragma unroll
    for (int j = 0; j < CHUNK; j++) {
        int idx = base + j;
        if (idx < N_NODES) {
            g_off[idx] = running;
            g_cur[idx] = running;
        }
        running += local[j];
    }
    if (tid == 1023) g_off[N_NODES] = running;
}

// ---------------------------------------------------------------------------
// k_fill: counting-sort edges by dst -> csr_src
// ---------------------------------------------------------------------------
__global__ void k_fill(const int* __restrict__ src,
                       const int* __restrict__ dst) {
    int e = blockIdx.x * blockDim.x + threadIdx.x;
    if (e < N_EDGES) {
        int d = dst[e];
        int pos = atomicAdd(&g_cur[d], 1);
        g_csrc[pos] = src[e];
    }
}

// ---------------------------------------------------------------------------
// k_gather: one warp per node. lane owns 4 consecutive floats (float4).
// h[v] = ndata[v] + (1/max(deg,1)) * sum_{s in N(v)} ndata[s]
// Register accumulation — no float atomics. Unroll x4 for MLP.
// ---------------------------------------------------------------------------
__global__ __launch_bounds__(256) void k_gather(const float* __restrict__ ndata) {
    int gt   = blockIdx.x * blockDim.x + threadIdx.x;
    int v    = gt >> 5;
    int lane = gt & 31;
    if (v >= N_NODES) return;

    int off0 = g_off[v];
    int off1 = g_off[v + 1];
    int d    = off1 - off0;
    float inv = 1.0f / (float)(d > 0 ? d : 1);

    float4 acc = make_float4(0.f, 0.f, 0.f, 0.f);

    int i = off0;
    for (; i + 4 <= off1; i += 4) {
        int s0 = __ldg(g_csrc + i);
        int s1 = __ldg(g_csrc + i + 1);
        int s2 = __ldg(g_csrc + i + 2);
        int s3 = __ldg(g_csrc + i + 3);
        float4 x0 = __ldg(reinterpret_cast<const float4*>(ndata + (size_t)s0 * DFEAT) + lane);
        float4 x1 = __ldg(reinterpret_cast<const float4*>(ndata + (size_t)s1 * DFEAT) + lane);
        float4 x2 = __ldg(reinterpret_cast<const float4*>(ndata + (size_t)s2 * DFEAT) + lane);
        float4 x3 = __ldg(reinterpret_cast<const float4*>(ndata + (size_t)s3 * DFEAT) + lane);
        acc.x += x0.x + x1.x + x2.x + x3.x;
        acc.y += x0.y + x1.y + x2.y + x3.y;
        acc.z += x0.z + x1.z + x2.z + x3.z;
        acc.w += x0.w + x1.w + x2.w + x3.w;
    }
    for (; i < off1; i++) {
        int s = __ldg(g_csrc + i);
        float4 x = __ldg(reinterpret_cast<const float4*>(ndata + (size_t)s * DFEAT) + lane);
        acc.x += x.x; acc.y += x.y; acc.z += x.z; acc.w += x.w;
    }

    float4 self = __ldg(reinterpret_cast<const float4*>(ndata + (size_t)v * DFEAT) + lane);
    float4 h;
    h.x = self.x + acc.x * inv;
    h.y = self.y + acc.y * inv;
    h.z = self.z + acc.z * inv;
    h.w = self.w + acc.w * inv;
    reinterpret_cast<float4*>(g_h + (size_t)v * DFEAT)[lane] = h;
}

// ---------------------------------------------------------------------------
// k_gemm: out[M,128] = h[M,128] @ W[128,128]^T + b
// BM=128, BN=128, BK=16, 256 threads, 8x8 microtile per thread.
// ---------------------------------------------------------------------------
__global__ __launch_bounds__(256) void k_gemm(const float* __restrict__ W,
                                              const float* __restrict__ b,
                                              float* __restrict__ out) {
    const int M = N_NODES;
    __shared__ float As[16][128];   // [k][m]
    __shared__ float Bs[16][128];   // [k][n]  (n = output col j; W[j][k])

    int tid = threadIdx.x;
    int blockRow = blockIdx.x * 128;
    int tr = tid >> 4;       // 0..15
    int tc = tid & 15;       // 0..15

    float acc[8][8];
#pragma unroll
    for (int i = 0; i < 8; i++)
#pragma unroll
        for (int j = 0; j < 8; j++) acc[i][j] = 0.0f;

#pragma unroll 1
    for (int k0 = 0; k0 < 128; k0 += 16) {
#pragma unroll
        for (int t = 0; t < 2; t++) {
            int idx = tid + t * 256;     // 0..511 (512 float4 per tile)
            int row = idx >> 2;          // 0..127
            int kq  = idx & 3;           // float4 index within BK=16

            int grow = blockRow + row;
            float4 v = make_float4(0.f, 0.f, 0.f, 0.f);
            if (grow < M)
                v = __ldg(reinterpret_cast<const float4*>(
                        g_h + (size_t)grow * 128 + k0) + kq);
            As[kq * 4 + 0][row] = v.x;
            As[kq * 4 + 1][row] = v.y;
            As[kq * 4 + 2][row] = v.z;
            As[kq * 4 + 3][row] = v.w;

            float4 w = __ldg(reinterpret_cast<const float4*>(
                    W + (size_t)row * 128 + k0) + kq);
            Bs[kq * 4 + 0][row] = w.x;
            Bs[kq * 4 + 1][row] = w.y;
            Bs[kq * 4 + 2][row] = w.z;
            Bs[kq * 4 + 3][row] = w.w;
        }
        __syncthreads();

#pragma unroll
        for (int k = 0; k < 16; k++) {
            float4 a0 = *reinterpret_cast<const float4*>(&As[k][tr * 8]);
            float4 a1 = *reinterpret_cast<const float4*>(&As[k][tr * 8 + 4]);
            float4 b0 = *reinterpret_cast<const float4*>(&Bs[k][tc * 8]);
            float4 b1 = *reinterpret_cast<const float4*>(&Bs[k][tc * 8 + 4]);
            float rm[8] = {a0.x, a0.y, a0.z, a0.w, a1.x, a1.y, a1.z, a1.w};
            float rn[8] = {b0.x, b0.y, b0.z, b0.w, b1.x, b1.y, b1.z, b1.w};
#pragma unroll
            for (int i = 0; i < 8; i++)
#pragma unroll
                for (int j = 0; j < 8; j++)
                    acc[i][j] += rm[i] * rn[j];
        }
        __syncthreads();
    }

    float bias[8];
#pragma unroll
    for (int j = 0; j < 8; j++) bias[j] = __ldg(b + tc * 8 + j);

#pragma unroll
    for (int i = 0; i < 8; i++) {
        int grow = blockRow + tr * 8 + i;
        if (grow < M) {
            float4 o0, o1;
            o0.x = acc[i][0] + bias[0];
            o0.y = acc[i][1] + bias[1];
            o0.z = acc[i][2] + bias[2];
            o0.w = acc[i][3] + bias[3];
            o1.x = acc[i][4] + bias[4];
            o1.y = acc[i][5] + bias[5];
            o1.z = acc[i][6] + bias[6];
            o1.w = acc[i][7] + bias[7];
            float4* op = reinterpret_cast<float4*>(out + (size_t)grow * 128 + tc * 8);
            op[0] = o0;
            op[1] = o1;
        }
    }
}

// ---------------------------------------------------------------------------
extern "C" void kernel_launch(void* const* d_in, const int* in_sizes, int n_in,
                              void* d_out, int out_size) {
    const float* ndata = (const float*)d_in[0];
    const int*   src   = (const int*)d_in[1];
    const int*   dst   = (const int*)d_in[2];
    const float* W     = (const float*)d_in[3];
    const float* b     = (const float*)d_in[4];
    float* out = (float*)d_out;

    (void)in_sizes; (void)n_in; (void)out_size;

    k_zero<<<(N_NODES + 255) / 256, 256>>>();
    k_deg<<<(N_EDGES + 255) / 256, 256>>>(dst);
    k_scan<<<1, 1024>>>();
    k_fill<<<(N_EDGES + 255) / 256, 256>>>(src, dst);
    {
        long long threads = (long long)N_NODES * 32;
        int blocks = (int)((threads + 255) / 256);
        k_gather<<<blocks, 256>>>(ndata);
    }
    {
        int blocks = (N_NODES + 127) / 128;
        k_gemm<<<blocks, 256>>>(W, b, out);
    }
}

// round 6
// speedup vs baseline: 1.9244x; 1.1453x over previous
#include <cuda_runtime.h>
#include <cuda_bf16.h>
#include <cstdint>

#define N_NODES 40000
#define DFEAT   128
#define N_EDGES 640000

// Scratch (static device globals — no allocation)
__device__ float g_h[N_NODES * DFEAT];    // h = ndata + mean(neighbors)
__device__ int   g_deg[N_NODES];
__device__ int   g_off[N_NODES + 1];      // CSR row offsets
__device__ int   g_cur[N_NODES];          // fill cursors
__device__ int   g_csrc[N_EDGES];         // CSR-ordered source indices

// ===========================================================================
// PTX helpers — baseline PTX only (sm_80+ mma.sync / sm_75+ ldmatrix),
// safe for the harness's compute_100 target (no tcgen05/sm_100a features).
// ===========================================================================
__device__ __forceinline__ uint32_t smem_u32(const void* p) {
    uint32_t a;
    asm("{ .reg .u64 t; cvta.to.shared.u64 t, %1; cvt.u32.u64 %0, t; }"
        : "=r"(a) : "l"(p));
    return a;
}

#define LDSM_X4(r0, r1, r2, r3, addr) \
    asm volatile("ldmatrix.sync.aligned.m8n8.x4.shared.b16 {%0,%1,%2,%3}, [%4];" \
                 : "=r"(r0), "=r"(r1), "=r"(r2), "=r"(r3) : "r"(addr))

#define MMA_BF16(c, a, b0, b1) \
    asm volatile("mma.sync.aligned.m16n8k16.row.col.f32.bf16.bf16.f32 " \
                 "{%0,%1,%2,%3}, {%4,%5,%6,%7}, {%8,%9}, {%0,%1,%2,%3};" \
                 : "+f"((c)[0]), "+f"((c)[1]), "+f"((c)[2]), "+f"((c)[3]) \
                 : "r"((a)[0]), "r"((a)[1]), "r"((a)[2]), "r"((a)[3]), \
                   "r"(b0), "r"(b1))

// ===========================================================================
// CSR construction + gather (unchanged — validated at 147.8us)
// ===========================================================================
__global__ void k_zero() {
    int i = blockIdx.x * blockDim.x + threadIdx.x;
    if (i < N_NODES) g_deg[i] = 0;
}

__global__ void k_deg(const int* __restrict__ dst) {
    int e = blockIdx.x * blockDim.x + threadIdx.x;
    if (e < N_EDGES) atomicAdd(&g_deg[dst[e]], 1);
}

__global__ __launch_bounds__(1024) void k_scan() {
    const int CHUNK = 40;
    __shared__ int partial[1024];
    int tid = threadIdx.x;
    int base = tid * CHUNK;

    int local[CHUNK];
    int sum = 0;
#pragma unroll
    for (int j = 0; j < CHUNK; j++) {
        int idx = base + j;
        int d = (idx < N_NODES) ? g_deg[idx] : 0;
        local[j] = d;
        sum += d;
    }
    partial[tid] = sum;
    __syncthreads();

    int val = sum;
    for (int s = 1; s < 1024; s <<= 1) {
        int other = (tid >= s) ? partial[tid - s] : 0;
        __syncthreads();
        val += other;
        partial[tid] = val;
        __syncthreads();
    }
    int excl = val - sum;

    int running = excl;
#pragma unroll
    for (int j = 0; j < CHUNK; j++) {
        int idx = base + j;
        if (idx < N_NODES) {
            g_off[idx] = running;
            g_cur[idx] = running;
        }
        running += local[j];
    }
    if (tid == 1023) g_off[N_NODES] = running;
}

__global__ void k_fill(const int* __restrict__ src,
                       const int* __restrict__ dst) {
    int e = blockIdx.x * blockDim.x + threadIdx.x;
    if (e < N_EDGES) {
        int d = dst[e];
        int pos = atomicAdd(&g_cur[d], 1);
        g_csrc[pos] = src[e];
    }
}

__global__ __launch_bounds__(256) void k_gather(const float* __restrict__ ndata) {
    int gt   = blockIdx.x * blockDim.x + threadIdx.x;
    int v    = gt >> 5;
    int lane = gt & 31;
    if (v >= N_NODES) return;

    int off0 = g_off[v];
    int off1 = g_off[v + 1];
    int d    = off1 - off0;
    float inv = 1.0f / (float)(d > 0 ? d : 1);

    float4 acc = make_float4(0.f, 0.f, 0.f, 0.f);

    int i = off0;
    for (; i + 4 <= off1; i += 4) {
        int s0 = __ldg(g_csrc + i);
        int s1 = __ldg(g_csrc + i + 1);
        int s2 = __ldg(g_csrc + i + 2);
        int s3 = __ldg(g_csrc + i + 3);
        float4 x0 = __ldg(reinterpret_cast<const float4*>(ndata + (size_t)s0 * DFEAT) + lane);
        float4 x1 = __ldg(reinterpret_cast<const float4*>(ndata + (size_t)s1 * DFEAT) + lane);
        float4 x2 = __ldg(reinterpret_cast<const float4*>(ndata + (size_t)s2 * DFEAT) + lane);
        float4 x3 = __ldg(reinterpret_cast<const float4*>(ndata + (size_t)s3 * DFEAT) + lane);
        acc.x += x0.x + x1.x + x2.x + x3.x;
        acc.y += x0.y + x1.y + x2.y + x3.y;
        acc.z += x0.z + x1.z + x2.z + x3.z;
        acc.w += x0.w + x1.w + x2.w + x3.w;
    }
    for (; i < off1; i++) {
        int s = __ldg(g_csrc + i);
        float4 x = __ldg(reinterpret_cast<const float4*>(ndata + (size_t)s * DFEAT) + lane);
        acc.x += x.x; acc.y += x.y; acc.z += x.z; acc.w += x.w;
    }

    float4 self = __ldg(reinterpret_cast<const float4*>(ndata + (size_t)v * DFEAT) + lane);
    float4 h;
    h.x = self.x + acc.x * inv;
    h.y = self.y + acc.y * inv;
    h.z = self.z + acc.z * inv;
    h.w = self.w + acc.w * inv;
    reinterpret_cast<float4*>(g_h + (size_t)v * DFEAT)[lane] = h;
}

// ===========================================================================
// k_gemm_mma: out[M,128] = h[M,128] @ W[128,128]^T + b
// bf16 split-precision (3 terms, fp32 accum) via mma.sync.m16n8k16.
//
// BM=128, BN=128, K staged in two 64-halves. 8 warps in 4x2 grid, warp tile
// 32x64. Staging tiles bf16, row stride 72 halves (144 B) -> conflict-free
// ldmatrix (9 mod 8 = 1 phase step).
// ===========================================================================
#define TSTRIDE     72                      // halves per row
#define TILE_BYTES  (128 * TSTRIDE * 2)     // 18432
#define A_HI_OFF    0
#define A_LO_OFF    (TILE_BYTES)
#define B_HI_OFF    (2 * TILE_BYTES)
#define B_LO_OFF    (3 * TILE_BYTES)
#define SMEM_TOTAL_MMA (4 * TILE_BYTES)     // 73728 B

__global__ __launch_bounds__(256, 2) void k_gemm_mma(const float* __restrict__ W,
                                                     const float* __restrict__ bias,
                                                     float* __restrict__ out) {
    extern __shared__ char smem[];
    uint32_t sb = smem_u32(smem);
    int tid  = threadIdx.x;
    int wid  = tid >> 5;
    int lane = tid & 31;
    int wm = wid & 3;          // 0..3: M sub-block (32 rows)
    int wn = wid >> 2;         // 0..1: N sub-block (64 cols)
    int blockRow = blockIdx.x * 128;

    float acc[2][8][4];
#pragma unroll
    for (int mt = 0; mt < 2; mt++)
#pragma unroll
        for (int nt = 0; nt < 8; nt++)
#pragma unroll
            for (int c = 0; c < 4; c++) acc[mt][nt][c] = 0.0f;

    for (int r = 0; r < 2; r++) {
        int k0 = r * 64;

        // --- stage: fp32 -> bf16 hi/lo tiles (A and B), padded rows --------
        for (int idx = tid; idx < 4096; idx += 256) {
            int isB = idx >> 11;
            int q   = idx & 2047;
            int row = q >> 4;            // 0..127
            int c4  = (q & 15) * 4;      // 0..60 step 4 (col within half)

            float4 v;
            if (isB) {
                v = __ldg(reinterpret_cast<const float4*>(W + (size_t)row * 128 + k0 + c4));
            } else {
                int grow = blockRow + row;
                if (grow < N_NODES)
                    v = __ldg(reinterpret_cast<const float4*>(g_h + (size_t)grow * 128 + k0 + c4));
                else
                    v = make_float4(0.f, 0.f, 0.f, 0.f);
            }

            __nv_bfloat16 h0 = __float2bfloat16(v.x);
            __nv_bfloat16 h1 = __float2bfloat16(v.y);
            __nv_bfloat16 h2 = __float2bfloat16(v.z);
            __nv_bfloat16 h3 = __float2bfloat16(v.w);
            __nv_bfloat16 l0 = __float2bfloat16(v.x - __bfloat162float(h0));
            __nv_bfloat16 l1 = __float2bfloat16(v.y - __bfloat162float(h1));
            __nv_bfloat16 l2 = __float2bfloat16(v.z - __bfloat162float(h2));
            __nv_bfloat16 l3 = __float2bfloat16(v.w - __bfloat162float(h3));

            uint32_t hiA = ((uint32_t)__bfloat16_as_ushort(h1) << 16) | __bfloat16_as_ushort(h0);
            uint32_t hiB = ((uint32_t)__bfloat16_as_ushort(h3) << 16) | __bfloat16_as_ushort(h2);
            uint32_t loA = ((uint32_t)__bfloat16_as_ushort(l1) << 16) | __bfloat16_as_ushort(l0);
            uint32_t loB = ((uint32_t)__bfloat16_as_ushort(l3) << 16) | __bfloat16_as_ushort(l2);

            uint32_t boff = (uint32_t)row * (TSTRIDE * 2) + (uint32_t)c4 * 2;
            int hiBase = isB ? B_HI_OFF : A_HI_OFF;
            int loBase = isB ? B_LO_OFF : A_LO_OFF;
            *reinterpret_cast<uint2*>(smem + hiBase + boff) = make_uint2(hiA, hiB);
            *reinterpret_cast<uint2*>(smem + loBase + boff) = make_uint2(loA, loB);
        }
        __syncthreads();

        // --- compute: 4 k16 steps ------------------------------------------
#pragma unroll
        for (int ks = 0; ks < 4; ks++) {
            int kk = ks * 16;

            // A fragments (2 m16 tiles, hi + lo)
            uint32_t a_hi[2][4], a_lo[2][4];
#pragma unroll
            for (int mt = 0; mt < 2; mt++) {
                int m = wm * 32 + mt * 16 + (lane & 15);
                uint32_t byteoff = (uint32_t)m * (TSTRIDE * 2) +
                                   (uint32_t)(kk + (lane >> 4) * 8) * 2;
                LDSM_X4(a_hi[mt][0], a_hi[mt][1], a_hi[mt][2], a_hi[mt][3],
                        sb + A_HI_OFF + byteoff);
                LDSM_X4(a_lo[mt][0], a_lo[mt][1], a_lo[mt][2], a_lo[mt][3],
                        sb + A_LO_OFF + byteoff);
            }

            // B fragments (4 groups of 2 n8 tiles, hi + lo)
            uint32_t b_hi[4][4], b_lo[4][4];
#pragma unroll
            for (int ng = 0; ng < 4; ng++) {
                int g = lane >> 3;       // 0..3
                int n = wn * 64 + ng * 16 + (g >> 1) * 8 + (lane & 7);
                uint32_t byteoff = (uint32_t)n * (TSTRIDE * 2) +
                                   (uint32_t)(kk + (g & 1) * 8) * 2;
                LDSM_X4(b_hi[ng][0], b_hi[ng][1], b_hi[ng][2], b_hi[ng][3],
                        sb + B_HI_OFF + byteoff);
                LDSM_X4(b_lo[ng][0], b_lo[ng][1], b_lo[ng][2], b_lo[ng][3],
                        sb + B_LO_OFF + byteoff);
            }

            // 3-term MMA
#pragma unroll
            for (int mt = 0; mt < 2; mt++) {
#pragma unroll
                for (int nt = 0; nt < 8; nt++) {
                    int ng = nt >> 1;
                    int hf = (nt & 1) * 2;
                    MMA_BF16(acc[mt][nt], a_hi[mt], b_hi[ng][hf], b_hi[ng][hf + 1]);
                    MMA_BF16(acc[mt][nt], a_hi[mt], b_lo[ng][hf], b_lo[ng][hf + 1]);
                    MMA_BF16(acc[mt][nt], a_lo[mt], b_hi[ng][hf], b_hi[ng][hf + 1]);
                }
            }
        }
        __syncthreads();
    }

    // --- epilogue: bias + direct stores ------------------------------------
#pragma unroll
    for (int mt = 0; mt < 2; mt++) {
        int r0 = blockRow + wm * 32 + mt * 16 + (lane >> 2);
        int r1 = r0 + 8;
#pragma unroll
        for (int nt = 0; nt < 8; nt++) {
            int cb = wn * 64 + nt * 8 + (lane & 3) * 2;
            float2 bb = *reinterpret_cast<const float2*>(bias + cb);
            if (r0 < N_NODES) {
                float2 o;
                o.x = acc[mt][nt][0] + bb.x;
                o.y = acc[mt][nt][1] + bb.y;
                *reinterpret_cast<float2*>(out + (size_t)r0 * 128 + cb) = o;
            }
            if (r1 < N_NODES) {
                float2 o;
                o.x = acc[mt][nt][2] + bb.x;
                o.y = acc[mt][nt][3] + bb.y;
                *reinterpret_cast<float2*>(out + (size_t)r1 * 128 + cb) = o;
            }
        }
    }
}

// ---------------------------------------------------------------------------
extern "C" void kernel_launch(void* const* d_in, const int* in_sizes, int n_in,
                              void* d_out, int out_size) {
    const float* ndata = (const float*)d_in[0];
    const int*   src   = (const int*)d_in[1];
    const int*   dst   = (const int*)d_in[2];
    const float* W     = (const float*)d_in[3];
    const float* b     = (const float*)d_in[4];
    float* out = (float*)d_out;

    (void)in_sizes; (void)n_in; (void)out_size;

    cudaFuncSetAttribute(k_gemm_mma, cudaFuncAttributeMaxDynamicSharedMemorySize,
                         SMEM_TOTAL_MMA);

    k_zero<<<(N_NODES + 255) / 256, 256>>>();
    k_deg<<<(N_EDGES + 255) / 256, 256>>>(dst);
    k_scan<<<1, 1024>>>();
    k_fill<<<(N_EDGES + 255) / 256, 256>>>(src, dst);
    {
        long long threads = (long long)N_NODES * 32;
        int blocks = (int)((threads + 255) / 256);
        k_gather<<<blocks, 256>>>(ndata);
    }
    {
        int blocks = (N_NODES + 127) / 128;   // 313
        k_gemm_mma<<<blocks, 256, SMEM_TOTAL_MMA>>>(W, b, out);
    }
}

// round 8
// speedup vs baseline: 2.0553x; 1.0681x over previous
#include <cuda_runtime.h>
#include <cuda_bf16.h>
#include <cstdint>

#define N_NODES 40000
#define DFEAT   128
#define N_EDGES 640000

// Scratch (static device globals — no allocation)
__device__ int   g_deg[N_NODES];
__device__ int   g_off[N_NODES + 1];        // CSR row offsets
__device__ int   g_cur[N_NODES];            // fill cursors
__device__ int   g_csrc[N_EDGES];           // CSR-ordered source indices
__device__ __nv_bfloat16 g_hh[N_NODES * DFEAT];   // h hi (bf16)
__device__ __nv_bfloat16 g_hl[N_NODES * DFEAT];   // h lo (bf16)
__device__ __nv_bfloat16 g_wh[DFEAT * DFEAT];     // W hi
__device__ __nv_bfloat16 g_wl[DFEAT * DFEAT];     // W lo

// ===========================================================================
// PTX helpers — baseline PTX only (sm_80+ mma.sync / sm_75+ ldmatrix).
// ===========================================================================
__device__ __forceinline__ uint32_t smem_u32(const void* p) {
    uint32_t a;
    asm("{ .reg .u64 t; cvta.to.shared.u64 t, %1; cvt.u32.u64 %0, t; }"
        : "=r"(a) : "l"(p));
    return a;
}

#define LDSM_X4(r0, r1, r2, r3, addr) \
    asm volatile("ldmatrix.sync.aligned.m8n8.x4.shared.b16 {%0,%1,%2,%3}, [%4];" \
                 : "=r"(r0), "=r"(r1), "=r"(r2), "=r"(r3) : "r"(addr))

#define MMA_BF16(c, a, b0, b1) \
    asm volatile("mma.sync.aligned.m16n8k16.row.col.f32.bf16.bf16.f32 " \
                 "{%0,%1,%2,%3}, {%4,%5,%6,%7}, {%8,%9}, {%0,%1,%2,%3};" \
                 : "+f"((c)[0]), "+f"((c)[1]), "+f"((c)[2]), "+f"((c)[3]) \
                 : "r"((a)[0]), "r"((a)[1]), "r"((a)[2]), "r"((a)[3]), \
                   "r"(b0), "r"(b1))

__device__ __forceinline__ uint32_t pack_hi2(float x, float y,
                                             float& rx, float& ry) {
    __nv_bfloat16 hx = __float2bfloat16(x);
    __nv_bfloat16 hy = __float2bfloat16(y);
    rx = x - __bfloat162float(hx);
    ry = y - __bfloat162float(hy);
    return ((uint32_t)__bfloat16_as_ushort(hy) << 16) | __bfloat16_as_ushort(hx);
}
__device__ __forceinline__ uint32_t pack_lo2(float rx, float ry) {
    __nv_bfloat16 lx = __float2bfloat16(rx);
    __nv_bfloat16 ly = __float2bfloat16(ry);
    return ((uint32_t)__bfloat16_as_ushort(ly) << 16) | __bfloat16_as_ushort(lx);
}

// ===========================================================================
// k_wsplit: W fp32 -> W_hi/W_lo bf16 (once)
// ===========================================================================
__global__ void k_wsplit(const float* __restrict__ W) {
    int i = blockIdx.x * blockDim.x + threadIdx.x;   // over float4, 4096 total
    if (i >= DFEAT * DFEAT / 4) return;
    float4 v = __ldg(reinterpret_cast<const float4*>(W) + i);
    float r0, r1, r2, r3;
    uint32_t hiA = pack_hi2(v.x, v.y, r0, r1);
    uint32_t hiB = pack_hi2(v.z, v.w, r2, r3);
    uint32_t loA = pack_lo2(r0, r1);
    uint32_t loB = pack_lo2(r2, r3);
    reinterpret_cast<uint2*>(g_wh)[i] = make_uint2(hiA, hiB);
    reinterpret_cast<uint2*>(g_wl)[i] = make_uint2(loA, loB);
}

// ===========================================================================
// CSR construction
// ===========================================================================
__global__ void k_zero() {
    int i = blockIdx.x * blockDim.x + threadIdx.x;
    if (i < N_NODES) g_deg[i] = 0;
}

__global__ void k_deg(const int* __restrict__ dst) {
    int t = blockIdx.x * blockDim.x + threadIdx.x;   // over groups of 4
    if (t < N_EDGES / 4) {
        int4 d = __ldg(reinterpret_cast<const int4*>(dst) + t);
        atomicAdd(&g_deg[d.x], 1);
        atomicAdd(&g_deg[d.y], 1);
        atomicAdd(&g_deg[d.z], 1);
        atomicAdd(&g_deg[d.w], 1);
    }
}

__global__ __launch_bounds__(1024) void k_scan() {
    const int CHUNK = 40;
    __shared__ int partial[1024];
    int tid = threadIdx.x;
    int base = tid * CHUNK;

    int local[CHUNK];
    int sum = 0;
#pragma unroll
    for (int j = 0; j < CHUNK; j++) {
        int idx = base + j;
        int d = (idx < N_NODES) ? g_deg[idx] : 0;
        local[j] = d;
        sum += d;
    }
    partial[tid] = sum;
    __syncthreads();

    int val = sum;
    for (int s = 1; s < 1024; s <<= 1) {
        int other = (tid >= s) ? partial[tid - s] : 0;
        __syncthreads();
        val += other;
        partial[tid] = val;
        __syncthreads();
    }
    int excl = val - sum;

    int running = excl;
#pragma unroll
    for (int j = 0; j < CHUNK; j++) {
        int idx = base + j;
        if (idx < N_NODES) {
            g_off[idx] = running;
            g_cur[idx] = running;
        }
        running += local[j];
    }
    if (tid == 1023) g_off[N_NODES] = running;
}

__global__ void k_fill(const int* __restrict__ src,
                       const int* __restrict__ dst) {
    int t = blockIdx.x * blockDim.x + threadIdx.x;   // over groups of 4
    if (t < N_EDGES / 4) {
        int4 d = __ldg(reinterpret_cast<const int4*>(dst) + t);
        int4 s = __ldg(reinterpret_cast<const int4*>(src) + t);
        g_csrc[atomicAdd(&g_cur[d.x], 1)] = s.x;
        g_csrc[atomicAdd(&g_cur[d.y], 1)] = s.y;
        g_csrc[atomicAdd(&g_cur[d.z], 1)] = s.z;
        g_csrc[atomicAdd(&g_cur[d.w], 1)] = s.w;
    }
}

// ===========================================================================
// k_gather: one warp per node; register accumulation; emits bf16 hi/lo of h.
// ===========================================================================
__global__ __launch_bounds__(256) void k_gather(const float* __restrict__ ndata) {
    int gt   = blockIdx.x * blockDim.x + threadIdx.x;
    int v    = gt >> 5;
    int lane = gt & 31;
    if (v >= N_NODES) return;

    int off0 = g_off[v];
    int off1 = g_off[v + 1];
    int d    = off1 - off0;
    float inv = 1.0f / (float)(d > 0 ? d : 1);

    float4 acc = make_float4(0.f, 0.f, 0.f, 0.f);

    int i = off0;
    for (; i + 4 <= off1; i += 4) {
        int s0 = __ldg(g_csrc + i);
        int s1 = __ldg(g_csrc + i + 1);
        int s2 = __ldg(g_csrc + i + 2);
        int s3 = __ldg(g_csrc + i + 3);
        float4 x0 = __ldg(reinterpret_cast<const float4*>(ndata + (size_t)s0 * DFEAT) + lane);
        float4 x1 = __ldg(reinterpret_cast<const float4*>(ndata + (size_t)s1 * DFEAT) + lane);
        float4 x2 = __ldg(reinterpret_cast<const float4*>(ndata + (size_t)s2 * DFEAT) + lane);
        float4 x3 = __ldg(reinterpret_cast<const float4*>(ndata + (size_t)s3 * DFEAT) + lane);
        acc.x += x0.x + x1.x + x2.x + x3.x;
        acc.y += x0.y + x1.y + x2.y + x3.y;
        acc.z += x0.z + x1.z + x2.z + x3.z;
        acc.w += x0.w + x1.w + x2.w + x3.w;
    }
    for (; i < off1; i++) {
        int s = __ldg(g_csrc + i);
        float4 x = __ldg(reinterpret_cast<const float4*>(ndata + (size_t)s * DFEAT) + lane);
        acc.x += x.x; acc.y += x.y; acc.z += x.z; acc.w += x.w;
    }

    float4 self = __ldg(reinterpret_cast<const float4*>(ndata + (size_t)v * DFEAT) + lane);
    float4 h;
    h.x = self.x + acc.x * inv;
    h.y = self.y + acc.y * inv;
    h.z = self.z + acc.z * inv;
    h.w = self.w + acc.w * inv;

    float r0, r1, r2, r3;
    uint32_t hiA = pack_hi2(h.x, h.y, r0, r1);
    uint32_t hiB = pack_hi2(h.z, h.w, r2, r3);
    uint32_t loA = pack_lo2(r0, r1);
    uint32_t loB = pack_lo2(r2, r3);

    size_t o = (size_t)v * DFEAT / 4 + lane;   // uint2 index
    reinterpret_cast<uint2*>(g_hh)[o] = make_uint2(hiA, hiB);
    reinterpret_cast<uint2*>(g_hl)[o] = make_uint2(loA, loB);
}

// ===========================================================================
// k_gemm_mma: out[40000,128] = h @ W^T + b  (bf16 split, 3 terms, fp32 accum)
//
// BM=160, BN=128; grid 250 (exactly 40000 rows — no bounds checks).
// 320 threads = 10 warps (5 M x 2 N), warp tile 32x64.
// K staged in two 64-halves; staging is pure 16B copies from precomputed
// bf16 hi/lo arrays. Padded rows (stride 72 halves) -> conflict-free ldmatrix.
// ===========================================================================
#define TSTRIDE   72
#define ROWB      (TSTRIDE * 2)                 // 144 B per row
#define A_HI_OFF  0
#define A_LO_OFF  (160 * ROWB)                  // 23040
#define B_HI_OFF  (2 * 160 * ROWB)              // 46080
#define B_LO_OFF  (B_HI_OFF + 128 * ROWB)       // 64512
#define SMEM_GEMM (B_LO_OFF + 128 * ROWB)       // 82944

__global__ __launch_bounds__(320, 2) void k_gemm_mma(const float* __restrict__ bias,
                                                     float* __restrict__ out) {
    extern __shared__ char smem[];
    uint32_t sb = smem_u32(smem);
    int tid  = threadIdx.x;
    int wid  = tid >> 5;
    int lane = tid & 31;
    int wm = wid % 5;          // 0..4: M sub-block (32 rows)
    int wn = wid / 5;          // 0..1: N sub-block (64 cols)
    int blockRow = blockIdx.x * 160;

    float acc[2][8][4];
#pragma unroll
    for (int mt = 0; mt < 2; mt++)
#pragma unroll
        for (int nt = 0; nt < 8; nt++)
#pragma unroll
            for (int c = 0; c < 4; c++) acc[mt][nt][c] = 0.0f;

    for (int r = 0; r < 2; r++) {
        int k0 = r * 64;

        // --- stage: pure copies, 16B each.  A: 2560 items, B: 2048 items ---
        for (int idx = tid; idx < 4608; idx += 320) {
            uint4 v;
            uint32_t soff;
            if (idx < 2560) {
                int isLo = idx >= 1280;
                int q    = isLo ? idx - 1280 : idx;
                int row  = q >> 3;
                int c8   = q & 7;
                const __nv_bfloat16* srcb = isLo ? g_hl : g_hh;
                v = __ldg(reinterpret_cast<const uint4*>(
                        srcb + (size_t)(blockRow + row) * DFEAT + k0) + c8);
                soff = (isLo ? A_LO_OFF : A_HI_OFF) + (uint32_t)row * ROWB + c8 * 16;
            } else {
                int q2   = idx - 2560;
                int isLo = q2 >= 1024;
                int q    = isLo ? q2 - 1024 : q2;
                int row  = q >> 3;
                int c8   = q & 7;
                const __nv_bfloat16* srcb = isLo ? g_wl : g_wh;
                v = __ldg(reinterpret_cast<const uint4*>(
                        srcb + (size_t)row * DFEAT + k0) + c8);
                soff = (isLo ? B_LO_OFF : B_HI_OFF) + (uint32_t)row * ROWB + c8 * 16;
            }
            *reinterpret_cast<uint4*>(smem + soff) = v;
        }
        __syncthreads();

        // --- compute: 4 k16 steps -----------------------------------------
#pragma unroll
        for (int ks = 0; ks < 4; ks++) {
            int kk = ks * 16;

            // A fragments (2 m16 tiles, hi + lo): 16 regs
            uint32_t a_hi[2][4], a_lo[2][4];
#pragma unroll
            for (int mt = 0; mt < 2; mt++) {
                int m = wm * 32 + mt * 16 + (lane & 15);
                uint32_t byteoff = (uint32_t)m * ROWB +
                                   (uint32_t)(kk + (lane >> 4) * 8) * 2;
                LDSM_X4(a_hi[mt][0], a_hi[mt][1], a_hi[mt][2], a_hi[mt][3],
                        sb + A_HI_OFF + byteoff);
                LDSM_X4(a_lo[mt][0], a_lo[mt][1], a_lo[mt][2], a_lo[mt][3],
                        sb + A_LO_OFF + byteoff);
            }

            // B per 16-col group: 8 regs live at a time
#pragma unroll
            for (int ng = 0; ng < 4; ng++) {
                int g = lane >> 3;
                int n = wn * 64 + ng * 16 + (g >> 1) * 8 + (lane & 7);
                uint32_t byteoff = (uint32_t)n * ROWB +
                                   (uint32_t)(kk + (g & 1) * 8) * 2;
                uint32_t b_hi[4], b_lo[4];
                LDSM_X4(b_hi[0], b_hi[1], b_hi[2], b_hi[3], sb + B_HI_OFF + byteoff);
                LDSM_X4(b_lo[0], b_lo[1], b_lo[2], b_lo[3], sb + B_LO_OFF + byteoff);
#pragma unroll
                for (int mt = 0; mt < 2; mt++) {
#pragma unroll
                    for (int h = 0; h < 2; h++) {
                        int nt = ng * 2 + h;
                        MMA_BF16(acc[mt][nt], a_hi[mt], b_hi[h * 2], b_hi[h * 2 + 1]);
                        MMA_BF16(acc[mt][nt], a_hi[mt], b_lo[h * 2], b_lo[h * 2 + 1]);
                        MMA_BF16(acc[mt][nt], a_lo[mt], b_hi[h * 2], b_hi[h * 2 + 1]);
                    }
                }
            }
        }
        __syncthreads();
    }

    // --- epilogue: bias + direct stores (no bounds checks; 250*160=40000) --
#pragma unroll
    for (int mt = 0; mt < 2; mt++) {
        int r0 = blockRow + wm * 32 + mt * 16 + (lane >> 2);
        int r1 = r0 + 8;
#pragma unroll
        for (int nt = 0; nt < 8; nt++) {
            int cb = wn * 64 + nt * 8 + (lane & 3) * 2;
            float2 bb = *reinterpret_cast<const float2*>(bias + cb);
            float2 o0, o1;
            o0.x = acc[mt][nt][0] + bb.x;
            o0.y = acc[mt][nt][1] + bb.y;
            o1.x = acc[mt][nt][2] + bb.x;
            o1.y = acc[mt][nt][3] + bb.y;
            *reinterpret_cast<float2*>(out + (size_t)r0 * 128 + cb) = o0;
            *reinterpret_cast<float2*>(out + (size_t)r1 * 128 + cb) = o1;
        }
    }
}

// ---------------------------------------------------------------------------
extern "C" void kernel_launch(void* const* d_in, const int* in_sizes, int n_in,
                              void* d_out, int out_size) {
    const float* ndata = (const float*)d_in[0];
    const int*   src   = (const int*)d_in[1];
    const int*   dst   = (const int*)d_in[2];
    const float* W     = (const float*)d_in[3];
    const float* b     = (const float*)d_in[4];
    float* out = (float*)d_out;

    (void)in_sizes; (void)n_in; (void)out_size;

    cudaFuncSetAttribute(k_gemm_mma, cudaFuncAttributeMaxDynamicSharedMemorySize,
                         SMEM_GEMM);

    k_wsplit<<<(DFEAT * DFEAT / 4 + 255) / 256, 256>>>(W);
    k_zero<<<(N_NODES + 255) / 256, 256>>>();
    k_deg<<<(N_EDGES / 4 + 255) / 256, 256>>>(dst);
    k_scan<<<1, 1024>>>();
    k_fill<<<(N_EDGES / 4 + 255) / 256, 256>>>(src, dst);
    {
        long long threads = (long long)N_NODES * 32;
        int blocks = (int)((threads + 255) / 256);
        k_gather<<<blocks, 256>>>(ndata);
    }
    k_gemm_mma<<<250, 320, SMEM_GEMM>>>(b, out);
}

// round 10
// speedup vs baseline: 3.2774x; 1.5946x over previous
#include <cuda_runtime.h>
#include <cuda_bf16.h>
#include <cstdint>

#define N_NODES 40000
#define DFEAT   128
#define N_EDGES 640000
#define SCAN_BLOCKS 40            // 40*1024 = 40960 >= 40000

// Scratch (static device globals — no allocation)
__device__ int   g_deg[N_NODES];
__device__ int   g_off[N_NODES + 1];        // CSR row offsets
__device__ int   g_cur[N_NODES];            // fill cursors
__device__ int   g_csrc[N_EDGES];           // CSR-ordered source indices
__device__ int   g_tmp[N_NODES];            // per-block exclusive prefixes
__device__ int   g_bsum[64];                // block totals
__device__ int   g_bpre[64];                // block exclusive prefixes
__device__ __nv_bfloat16 g_hh[N_NODES * DFEAT];   // h hi (bf16)
__device__ __nv_bfloat16 g_hl[N_NODES * DFEAT];   // h lo (bf16)
__device__ __nv_bfloat16 g_wh[DFEAT * DFEAT];     // W hi
__device__ __nv_bfloat16 g_wl[DFEAT * DFEAT];     // W lo

// ===========================================================================
// PTX helpers — baseline PTX only (sm_80+ mma.sync / sm_75+ ldmatrix).
// ===========================================================================
__device__ __forceinline__ uint32_t smem_u32(const void* p) {
    uint32_t a;
    asm("{ .reg .u64 t; cvta.to.shared.u64 t, %1; cvt.u32.u64 %0, t; }"
        : "=r"(a) : "l"(p));
    return a;
}

#define LDSM_X4(r0, r1, r2, r3, addr) \
    asm volatile("ldmatrix.sync.aligned.m8n8.x4.shared.b16 {%0,%1,%2,%3}, [%4];" \
                 : "=r"(r0), "=r"(r1), "=r"(r2), "=r"(r3) : "r"(addr))

#define MMA_BF16(c, a, b0, b1) \
    asm volatile("mma.sync.aligned.m16n8k16.row.col.f32.bf16.bf16.f32 " \
                 "{%0,%1,%2,%3}, {%4,%5,%6,%7}, {%8,%9}, {%0,%1,%2,%3};" \
                 : "+f"((c)[0]), "+f"((c)[1]), "+f"((c)[2]), "+f"((c)[3]) \
                 : "r"((a)[0]), "r"((a)[1]), "r"((a)[2]), "r"((a)[3]), \
                   "r"(b0), "r"(b1))

__device__ __forceinline__ uint32_t pack_hi2(float x, float y,
                                             float& rx, float& ry) {
    __nv_bfloat16 hx = __float2bfloat16(x);
    __nv_bfloat16 hy = __float2bfloat16(y);
    rx = x - __bfloat162float(hx);
    ry = y - __bfloat162float(hy);
    return ((uint32_t)__bfloat16_as_ushort(hy) << 16) | __bfloat16_as_ushort(hx);
}
__device__ __forceinline__ uint32_t pack_lo2(float rx, float ry) {
    __nv_bfloat16 lx = __float2bfloat16(rx);
    __nv_bfloat16 ly = __float2bfloat16(ry);
    return ((uint32_t)__bfloat16_as_ushort(ly) << 16) | __bfloat16_as_ushort(lx);
}

// ===========================================================================
// k_wsplit: W fp32 -> W_hi/W_lo bf16 (once)
// ===========================================================================
__global__ void k_wsplit(const float* __restrict__ W) {
    int i = blockIdx.x * blockDim.x + threadIdx.x;   // over float4, 4096 total
    if (i >= DFEAT * DFEAT / 4) return;
    float4 v = __ldg(reinterpret_cast<const float4*>(W) + i);
    float r0, r1, r2, r3;
    uint32_t hiA = pack_hi2(v.x, v.y, r0, r1);
    uint32_t hiB = pack_hi2(v.z, v.w, r2, r3);
    uint32_t loA = pack_lo2(r0, r1);
    uint32_t loB = pack_lo2(r2, r3);
    reinterpret_cast<uint2*>(g_wh)[i] = make_uint2(hiA, hiB);
    reinterpret_cast<uint2*>(g_wl)[i] = make_uint2(loA, loB);
}

// ===========================================================================
// CSR construction
// ===========================================================================
__global__ void k_zero() {
    int i = blockIdx.x * blockDim.x + threadIdx.x;
    if (i < N_NODES) g_deg[i] = 0;
}

__global__ void k_deg(const int* __restrict__ dst) {
    int t = blockIdx.x * blockDim.x + threadIdx.x;   // over groups of 4
    if (t < N_EDGES / 4) {
        int4 d = __ldg(reinterpret_cast<const int4*>(dst) + t);
        atomicAdd(&g_deg[d.x], 1);
        atomicAdd(&g_deg[d.y], 1);
        atomicAdd(&g_deg[d.z], 1);
        atomicAdd(&g_deg[d.w], 1);
    }
}

// --- multi-block scan: phase 1 — block-local scan --------------------------
__global__ __launch_bounds__(1024) void k_scan1() {
    __shared__ int sh[1024];
    int b = blockIdx.x, tid = threadIdx.x;
    int i = b * 1024 + tid;
    int v = (i < N_NODES) ? g_deg[i] : 0;
    int val = v;
    sh[tid] = val;
    __syncthreads();
    for (int s = 1; s < 1024; s <<= 1) {
        int o = (tid >= s) ? sh[tid - s] : 0;
        __syncthreads();
        val += o;
        sh[tid] = val;
        __syncthreads();
    }
    if (i < N_NODES) g_tmp[i] = val - v;     // block-local exclusive
    if (tid == 1023) g_bsum[b] = val;        // block total
}

// --- phase 2 — scan the 40 block totals ------------------------------------
__global__ void k_scan2() {
    __shared__ int sh[64];
    int tid = threadIdx.x;                   // 64 threads
    int v = (tid < SCAN_BLOCKS) ? g_bsum[tid] : 0;
    int val = v;
    sh[tid] = val;
    __syncthreads();
    for (int s = 1; s < 64; s <<= 1) {
        int o = (tid >= s) ? sh[tid - s] : 0;
        __syncthreads();
        val += o;
        sh[tid] = val;
        __syncthreads();
    }
    g_bpre[tid] = val - v;                   // exclusive
    if (tid == SCAN_BLOCKS - 1) g_off[N_NODES] = val;   // grand total
}

// --- phase 3 — combine -------------------------------------------------------
__global__ __launch_bounds__(1024) void k_scan3() {
    int b = blockIdx.x, tid = threadIdx.x;
    int i = b * 1024 + tid;
    if (i < N_NODES) {
        int o = g_tmp[i] + g_bpre[b];
        g_off[i] = o;
        g_cur[i] = o;
    }
}

__global__ void k_fill(const int* __restrict__ src,
                       const int* __restrict__ dst) {
    int t = blockIdx.x * blockDim.x + threadIdx.x;   // over groups of 4
    if (t < N_EDGES / 4) {
        int4 d = __ldg(reinterpret_cast<const int4*>(dst) + t);
        int4 s = __ldg(reinterpret_cast<const int4*>(src) + t);
        g_csrc[atomicAdd(&g_cur[d.x], 1)] = s.x;
        g_csrc[atomicAdd(&g_cur[d.y], 1)] = s.y;
        g_csrc[atomicAdd(&g_cur[d.z], 1)] = s.z;
        g_csrc[atomicAdd(&g_cur[d.w], 1)] = s.w;
    }
}

// ===========================================================================
// k_gather: one warp per node; register accumulation; emits bf16 hi/lo of h.
// ===========================================================================
__global__ __launch_bounds__(256) void k_gather(const float* __restrict__ ndata) {
    int gt   = blockIdx.x * blockDim.x + threadIdx.x;
    int v    = gt >> 5;
    int lane = gt & 31;
    if (v >= N_NODES) return;

    int off0 = g_off[v];
    int off1 = g_off[v + 1];
    int d    = off1 - off0;
    float inv = 1.0f / (float)(d > 0 ? d : 1);

    float4 acc = make_float4(0.f, 0.f, 0.f, 0.f);

    int i = off0;
    for (; i + 4 <= off1; i += 4) {
        int s0 = __ldg(g_csrc + i);
        int s1 = __ldg(g_csrc + i + 1);
        int s2 = __ldg(g_csrc + i + 2);
        int s3 = __ldg(g_csrc + i + 3);
        float4 x0 = __ldg(reinterpret_cast<const float4*>(ndata + (size_t)s0 * DFEAT) + lane);
        float4 x1 = __ldg(reinterpret_cast<const float4*>(ndata + (size_t)s1 * DFEAT) + lane);
        float4 x2 = __ldg(reinterpret_cast<const float4*>(ndata + (size_t)s2 * DFEAT) + lane);
        float4 x3 = __ldg(reinterpret_cast<const float4*>(ndata + (size_t)s3 * DFEAT) + lane);
        acc.x += x0.x + x1.x + x2.x + x3.x;
        acc.y += x0.y + x1.y + x2.y + x3.y;
        acc.z += x0.z + x1.z + x2.z + x3.z;
        acc.w += x0.w + x1.w + x2.w + x3.w;
    }
    for (; i < off1; i++) {
        int s = __ldg(g_csrc + i);
        float4 x = __ldg(reinterpret_cast<const float4*>(ndata + (size_t)s * DFEAT) + lane);
        acc.x += x.x; acc.y += x.y; acc.z += x.z; acc.w += x.w;
    }

    float4 self = __ldg(reinterpret_cast<const float4*>(ndata + (size_t)v * DFEAT) + lane);
    float4 h;
    h.x = self.x + acc.x * inv;
    h.y = self.y + acc.y * inv;
    h.z = self.z + acc.z * inv;
    h.w = self.w + acc.w * inv;

    float r0, r1, r2, r3;
    uint32_t hiA = pack_hi2(h.x, h.y, r0, r1);
    uint32_t hiB = pack_hi2(h.z, h.w, r2, r3);
    uint32_t loA = pack_lo2(r0, r1);
    uint32_t loB = pack_lo2(r2, r3);

    size_t o = (size_t)v * DFEAT / 4 + lane;   // uint2 index
    reinterpret_cast<uint2*>(g_hh)[o] = make_uint2(hiA, hiB);
    reinterpret_cast<uint2*>(g_hl)[o] = make_uint2(loA, loB);
}

// ===========================================================================
// k_gemm_mma: out[40000,128] = h @ W^T + b  (bf16 split, 3 terms, fp32 accum)
// BM=160, BN=128; grid 250; 320 threads = 10 warps (5 M x 2 N).
// ===========================================================================
#define TSTRIDE   72
#define ROWB      (TSTRIDE * 2)                 // 144 B per row
#define A_HI_OFF  0
#define A_LO_OFF  (160 * ROWB)                  // 23040
#define B_HI_OFF  (2 * 160 * ROWB)              // 46080
#define B_LO_OFF  (B_HI_OFF + 128 * ROWB)       // 64512
#define SMEM_GEMM (B_LO_OFF + 128 * ROWB)       // 82944

__global__ __launch_bounds__(320, 2) void k_gemm_mma(const float* __restrict__ bias,
                                                     float* __restrict__ out) {
    extern __shared__ char smem[];
    uint32_t sb = smem_u32(smem);
    int tid  = threadIdx.x;
    int wid  = tid >> 5;
    int lane = tid & 31;
    int wm = wid % 5;
    int wn = wid / 5;
    int blockRow = blockIdx.x * 160;

    float acc[2][8][4];
#pragma unroll
    for (int mt = 0; mt < 2; mt++)
#pragma unroll
        for (int nt = 0; nt < 8; nt++)
#pragma unroll
            for (int c = 0; c < 4; c++) acc[mt][nt][c] = 0.0f;

    for (int r = 0; r < 2; r++) {
        int k0 = r * 64;

        for (int idx = tid; idx < 4608; idx += 320) {
            uint4 v;
            uint32_t soff;
            if (idx < 2560) {
                int isLo = idx >= 1280;
                int q    = isLo ? idx - 1280 : idx;
                int row  = q >> 3;
                int c8   = q & 7;
                const __nv_bfloat16* srcb = isLo ? g_hl : g_hh;
                v = __ldg(reinterpret_cast<const uint4*>(
                        srcb + (size_t)(blockRow + row) * DFEAT + k0) + c8);
                soff = (isLo ? A_LO_OFF : A_HI_OFF) + (uint32_t)row * ROWB + c8 * 16;
            } else {
                int q2   = idx - 2560;
                int isLo = q2 >= 1024;
                int q    = isLo ? q2 - 1024 : q2;
                int row  = q >> 3;
                int c8   = q & 7;
                const __nv_bfloat16* srcb = isLo ? g_wl : g_wh;
                v = __ldg(reinterpret_cast<const uint4*>(
                        srcb + (size_t)row * DFEAT + k0) + c8);
                soff = (isLo ? B_LO_OFF : B_HI_OFF) + (uint32_t)row * ROWB + c8 * 16;
            }
            *reinterpret_cast<uint4*>(smem + soff) = v;
        }
        __syncthreads();

#pragma unroll
        for (int ks = 0; ks < 4; ks++) {
            int kk = ks * 16;

            uint32_t a_hi[2][4], a_lo[2][4];
#pragma unroll
            for (int mt = 0; mt < 2; mt++) {
                int m = wm * 32 + mt * 16 + (lane & 15);
                uint32_t byteoff = (uint32_t)m * ROWB +
                                   (uint32_t)(kk + (lane >> 4) * 8) * 2;
                LDSM_X4(a_hi[mt][0], a_hi[mt][1], a_hi[mt][2], a_hi[mt][3],
                        sb + A_HI_OFF + byteoff);
                LDSM_X4(a_lo[mt][0], a_lo[mt][1], a_lo[mt][2], a_lo[mt][3],
                        sb + A_LO_OFF + byteoff);
            }

#pragma unroll
            for (int ng = 0; ng < 4; ng++) {
                int g = lane >> 3;
                int n = wn * 64 + ng * 16 + (g >> 1) * 8 + (lane & 7);
                uint32_t byteoff = (uint32_t)n * ROWB +
                                   (uint32_t)(kk + (g & 1) * 8) * 2;
                uint32_t b_hi[4], b_lo[4];
                LDSM_X4(b_hi[0], b_hi[1], b_hi[2], b_hi[3], sb + B_HI_OFF + byteoff);
                LDSM_X4(b_lo[0], b_lo[1], b_lo[2], b_lo[3], sb + B_LO_OFF + byteoff);
#pragma unroll
                for (int mt = 0; mt < 2; mt++) {
#pragma unroll
                    for (int h = 0; h < 2; h++) {
                        int nt = ng * 2 + h;
                        MMA_BF16(acc[mt][nt], a_hi[mt], b_hi[h * 2], b_hi[h * 2 + 1]);
                        MMA_BF16(acc[mt][nt], a_hi[mt], b_lo[h * 2], b_lo[h * 2 + 1]);
                        MMA_BF16(acc[mt][nt], a_lo[mt], b_hi[h * 2], b_hi[h * 2 + 1]);
                    }
                }
            }
        }
        __syncthreads();
    }

#pragma unroll
    for (int mt = 0; mt < 2; mt++) {
        int r0 = blockRow + wm * 32 + mt * 16 + (lane >> 2);
        int r1 = r0 + 8;
#pragma unroll
        for (int nt = 0; nt < 8; nt++) {
            int cb = wn * 64 + nt * 8 + (lane & 3) * 2;
            float2 bb = *reinterpret_cast<const float2*>(bias + cb);
            float2 o0, o1;
            o0.x = acc[mt][nt][0] + bb.x;
            o0.y = acc[mt][nt][1] + bb.y;
            o1.x = acc[mt][nt][2] + bb.x;
            o1.y = acc[mt][nt][3] + bb.y;
            *reinterpret_cast<float2*>(out + (size_t)r0 * 128 + cb) = o0;
            *reinterpret_cast<float2*>(out + (size_t)r1 * 128 + cb) = o1;
        }
    }
}

// ---------------------------------------------------------------------------
extern "C" void kernel_launch(void* const* d_in, const int* in_sizes, int n_in,
                              void* d_out, int out_size) {
    const float* ndata = (const float*)d_in[0];
    const int*   src   = (const int*)d_in[1];
    const int*   dst   = (const int*)d_in[2];
    const float* W     = (const float*)d_in[3];
    const float* b     = (const float*)d_in[4];
    float* out = (float*)d_out;

    (void)in_sizes; (void)n_in; (void)out_size;

    cudaFuncSetAttribute(k_gemm_mma, cudaFuncAttributeMaxDynamicSharedMemorySize,
                         SMEM_GEMM);

    k_wsplit<<<(DFEAT * DFEAT / 4 + 255) / 256, 256>>>(W);
    k_zero<<<(N_NODES + 255) / 256, 256>>>();
    k_deg<<<(N_EDGES / 4 + 255) / 256, 256>>>(dst);
    k_scan1<<<SCAN_BLOCKS, 1024>>>();
    k_scan2<<<1, 64>>>();
    k_scan3<<<SCAN_BLOCKS, 1024>>>();
    k_fill<<<(N_EDGES / 4 + 255) / 256, 256>>>(src, dst);
    {
        long long threads = (long long)N_NODES * 32;
        int blocks = (int)((threads + 255) / 256);
        k_gather<<<blocks, 256>>>(ndata);
    }
    k_gemm_mma<<<250, 320, SMEM_GEMM>>>(b, out);
}

// round 12
// speedup vs baseline: 3.3685x; 1.0278x over previous
#include <cuda_runtime.h>
#include <cuda_bf16.h>
#include <cstdint>

#define N_NODES 40000
#define DFEAT   128
#define N_EDGES 640000
#define SCAN_BLOCKS 40            // 40*1024 = 40960 >= 40000

// Scratch (static device globals — no allocation)
__device__ int   g_deg[N_NODES];
__device__ int   g_off[N_NODES + 1];        // CSR row offsets
__device__ int   g_rank[N_EDGES];           // per-edge rank within dst node
__device__ int   g_csrc[N_EDGES];           // CSR-ordered source indices
__device__ int   g_tmp[N_NODES];            // per-block exclusive prefixes
__device__ int   g_bsum[64];                // block totals
__device__ int   g_bpre[64];                // block exclusive prefixes
__device__ __nv_bfloat16 g_hh[N_NODES * DFEAT];   // h hi (bf16)
__device__ __nv_bfloat16 g_hl[N_NODES * DFEAT];   // h lo (bf16)
__device__ __nv_bfloat16 g_wh[DFEAT * DFEAT];     // W hi
__device__ __nv_bfloat16 g_wl[DFEAT * DFEAT];     // W lo

// ===========================================================================
// PTX helpers — baseline PTX only (sm_80+ mma.sync / sm_75+ ldmatrix).
// ===========================================================================
__device__ __forceinline__ uint32_t smem_u32(const void* p) {
    uint32_t a;
    asm("{ .reg .u64 t; cvta.to.shared.u64 t, %1; cvt.u32.u64 %0, t; }"
        : "=r"(a) : "l"(p));
    return a;
}

#define LDSM_X4(r0, r1, r2, r3, addr) \
    asm volatile("ldmatrix.sync.aligned.m8n8.x4.shared.b16 {%0,%1,%2,%3}, [%4];" \
                 : "=r"(r0), "=r"(r1), "=r"(r2), "=r"(r3) : "r"(addr))

#define MMA_BF16(c, a, b0, b1) \
    asm volatile("mma.sync.aligned.m16n8k16.row.col.f32.bf16.bf16.f32 " \
                 "{%0,%1,%2,%3}, {%4,%5,%6,%7}, {%8,%9}, {%0,%1,%2,%3};" \
                 : "+f"((c)[0]), "+f"((c)[1]), "+f"((c)[2]), "+f"((c)[3]) \
                 : "r"((a)[0]), "r"((a)[1]), "r"((a)[2]), "r"((a)[3]), \
                   "r"(b0), "r"(b1))

__device__ __forceinline__ uint32_t pack_hi2(float x, float y,
                                             float& rx, float& ry) {
    __nv_bfloat16 hx = __float2bfloat16(x);
    __nv_bfloat16 hy = __float2bfloat16(y);
    rx = x - __bfloat162float(hx);
    ry = y - __bfloat162float(hy);
    return ((uint32_t)__bfloat16_as_ushort(hy) << 16) | __bfloat16_as_ushort(hx);
}
__device__ __forceinline__ uint32_t pack_lo2(float rx, float ry) {
    __nv_bfloat16 lx = __float2bfloat16(rx);
    __nv_bfloat16 ly = __float2bfloat16(ry);
    return ((uint32_t)__bfloat16_as_ushort(ly) << 16) | __bfloat16_as_ushort(lx);
}

// ===========================================================================
// k_init: fused  W fp32 -> bf16 hi/lo split  +  deg = 0
// ===========================================================================
__global__ void k_init(const float* __restrict__ W) {
    int i = blockIdx.x * blockDim.x + threadIdx.x;
    if (i < DFEAT * DFEAT / 4) {
        float4 v = __ldg(reinterpret_cast<const float4*>(W) + i);
        float r0, r1, r2, r3;
        uint32_t hiA = pack_hi2(v.x, v.y, r0, r1);
        uint32_t hiB = pack_hi2(v.z, v.w, r2, r3);
        uint32_t loA = pack_lo2(r0, r1);
        uint32_t loB = pack_lo2(r2, r3);
        reinterpret_cast<uint2*>(g_wh)[i] = make_uint2(hiA, hiB);
        reinterpret_cast<uint2*>(g_wl)[i] = make_uint2(loA, loB);
    }
    if (i < N_NODES) g_deg[i] = 0;
}

// ===========================================================================
// k_deg: in-degree histogram + per-edge rank capture (single atomic pass)
// ===========================================================================
__global__ void k_deg(const int* __restrict__ dst) {
    int t = blockIdx.x * blockDim.x + threadIdx.x;   // over groups of 4
    if (t < N_EDGES / 4) {
        int4 d = __ldg(reinterpret_cast<const int4*>(dst) + t);
        int4 r;
        r.x = atomicAdd(&g_deg[d.x], 1);
        r.y = atomicAdd(&g_deg[d.y], 1);
        r.z = atomicAdd(&g_deg[d.z], 1);
        r.w = atomicAdd(&g_deg[d.w], 1);
        reinterpret_cast<int4*>(g_rank)[t] = r;
    }
}

// --- multi-block scan: phase 1 — block-local scan --------------------------
__global__ __launch_bounds__(1024) void k_scan1() {
    __shared__ int sh[1024];
    int b = blockIdx.x, tid = threadIdx.x;
    int i = b * 1024 + tid;
    int v = (i < N_NODES) ? g_deg[i] : 0;
    int val = v;
    sh[tid] = val;
    __syncthreads();
    for (int s = 1; s < 1024; s <<= 1) {
        int o = (tid >= s) ? sh[tid - s] : 0;
        __syncthreads();
        val += o;
        sh[tid] = val;
        __syncthreads();
    }
    if (i < N_NODES) g_tmp[i] = val - v;     // block-local exclusive
    if (tid == 1023) g_bsum[b] = val;        // block total
}

// --- phase 2 — scan the 40 block totals ------------------------------------
__global__ void k_scan2() {
    __shared__ int sh[64];
    int tid = threadIdx.x;                   // 64 threads
    int v = (tid < SCAN_BLOCKS) ? g_bsum[tid] : 0;
    int val = v;
    sh[tid] = val;
    __syncthreads();
    for (int s = 1; s < 64; s <<= 1) {
        int o = (tid >= s) ? sh[tid - s] : 0;
        __syncthreads();
        val += o;
        sh[tid] = val;
        __syncthreads();
    }
    g_bpre[tid] = val - v;                   // exclusive
    if (tid == SCAN_BLOCKS - 1) g_off[N_NODES] = val;   // grand total
}

// --- phase 3 — combine -------------------------------------------------------
__global__ __launch_bounds__(1024) void k_scan3() {
    int b = blockIdx.x, tid = threadIdx.x;
    int i = b * 1024 + tid;
    if (i < N_NODES) g_off[i] = g_tmp[i] + g_bpre[b];
}

// ===========================================================================
// k_fill: atomic-free scatter — position = g_off[dst] + rank
// ===========================================================================
__global__ void k_fill(const int* __restrict__ src,
                       const int* __restrict__ dst) {
    int t = blockIdx.x * blockDim.x + threadIdx.x;   // over groups of 4
    if (t < N_EDGES / 4) {
        int4 d = __ldg(reinterpret_cast<const int4*>(dst) + t);
        int4 s = __ldg(reinterpret_cast<const int4*>(src) + t);
        int4 r = __ldg(reinterpret_cast<const int4*>(g_rank) + t);
        g_csrc[__ldg(&g_off[d.x]) + r.x] = s.x;
        g_csrc[__ldg(&g_off[d.y]) + r.y] = s.y;
        g_csrc[__ldg(&g_off[d.z]) + r.z] = s.z;
        g_csrc[__ldg(&g_off[d.w]) + r.w] = s.w;
    }
}

// ===========================================================================
// k_gather: one warp per node; register accumulation; emits bf16 hi/lo of h.
// ===========================================================================
__global__ __launch_bounds__(256) void k_gather(const float* __restrict__ ndata) {
    int gt   = blockIdx.x * blockDim.x + threadIdx.x;
    int v    = gt >> 5;
    int lane = gt & 31;
    if (v >= N_NODES) return;

    int off0 = g_off[v];
    int off1 = g_off[v + 1];
    int d    = off1 - off0;
    float inv = 1.0f / (float)(d > 0 ? d : 1);

    float4 acc = make_float4(0.f, 0.f, 0.f, 0.f);

    int i = off0;
    for (; i + 4 <= off1; i += 4) {
        int s0 = __ldg(g_csrc + i);
        int s1 = __ldg(g_csrc + i + 1);
        int s2 = __ldg(g_csrc + i + 2);
        int s3 = __ldg(g_csrc + i + 3);
        float4 x0 = __ldg(reinterpret_cast<const float4*>(ndata + (size_t)s0 * DFEAT) + lane);
        float4 x1 = __ldg(reinterpret_cast<const float4*>(ndata + (size_t)s1 * DFEAT) + lane);
        float4 x2 = __ldg(reinterpret_cast<const float4*>(ndata + (size_t)s2 * DFEAT) + lane);
        float4 x3 = __ldg(reinterpret_cast<const float4*>(ndata + (size_t)s3 * DFEAT) + lane);
        acc.x += x0.x + x1.x + x2.x + x3.x;
        acc.y += x0.y + x1.y + x2.y + x3.y;
        acc.z += x0.z + x1.z + x2.z + x3.z;
        acc.w += x0.w + x1.w + x2.w + x3.w;
    }
    for (; i < off1; i++) {
        int s = __ldg(g_csrc + i);
        float4 x = __ldg(reinterpret_cast<const float4*>(ndata + (size_t)s * DFEAT) + lane);
        acc.x += x.x; acc.y += x.y; acc.z += x.z; acc.w += x.w;
    }

    float4 self = __ldg(reinterpret_cast<const float4*>(ndata + (size_t)v * DFEAT) + lane);
    float4 h;
    h.x = self.x + acc.x * inv;
    h.y = self.y + acc.y * inv;
    h.z = self.z + acc.z * inv;
    h.w = self.w + acc.w * inv;

    float r0, r1, r2, r3;
    uint32_t hiA = pack_hi2(h.x, h.y, r0, r1);
    uint32_t hiB = pack_hi2(h.z, h.w, r2, r3);
    uint32_t loA = pack_lo2(r0, r1);
    uint32_t loB = pack_lo2(r2, r3);

    size_t o = (size_t)v * DFEAT / 4 + lane;   // uint2 index
    reinterpret_cast<uint2*>(g_hh)[o] = make_uint2(hiA, hiB);
    reinterpret_cast<uint2*>(g_hl)[o] = make_uint2(loA, loB);
}

// ===========================================================================
// k_gemm_mma: out[40000,128] = h @ W^T + b  (bf16 split, 3 terms, fp32 accum)
// BM=160, BN=128; grid 250; 320 threads = 10 warps (5 M x 2 N).
// ===========================================================================
#define TSTRIDE   72
#define ROWB      (TSTRIDE * 2)                 // 144 B per row
#define A_HI_OFF  0
#define A_LO_OFF  (160 * ROWB)                  // 23040
#define B_HI_OFF  (2 * 160 * ROWB)              // 46080
#define B_LO_OFF  (B_HI_OFF + 128 * ROWB)       // 64512
#define SMEM_GEMM (B_LO_OFF + 128 * ROWB)       // 82944

__global__ __launch_bounds__(320, 2) void k_gemm_mma(const float* __restrict__ bias,
                                                     float* __restrict__ out) {
    extern __shared__ char smem[];
    uint32_t sb = smem_u32(smem);
    int tid  = threadIdx.x;
    int wid  = tid >> 5;
    int lane = tid & 31;
    int wm = wid % 5;
    int wn = wid / 5;
    int blockRow = blockIdx.x * 160;

    float acc[2][8][4];
#pragma unroll
    for (int mt = 0; mt < 2; mt++)
#pragma unroll
        for (int nt = 0; nt < 8; nt++)
#pragma unroll
            for (int c = 0; c < 4; c++) acc[mt][nt][c] = 0.0f;

    for (int r = 0; r < 2; r++) {
        int k0 = r * 64;

        for (int idx = tid; idx < 4608; idx += 320) {
            uint4 v;
            uint32_t soff;
            if (idx < 2560) {
                int isLo = idx >= 1280;
                int q    = isLo ? idx - 1280 : idx;
                int row  = q >> 3;
                int c8   = q & 7;
                const __nv_bfloat16* srcb = isLo ? g_hl : g_hh;
                v = __ldg(reinterpret_cast<const uint4*>(
                        srcb + (size_t)(blockRow + row) * DFEAT + k0) + c8);
                soff = (isLo ? A_LO_OFF : A_HI_OFF) + (uint32_t)row * ROWB + c8 * 16;
            } else {
                int q2   = idx - 2560;
                int isLo = q2 >= 1024;
                int q    = isLo ? q2 - 1024 : q2;
                int row  = q >> 3;
                int c8   = q & 7;
                const __nv_bfloat16* srcb = isLo ? g_wl : g_wh;
                v = __ldg(reinterpret_cast<const uint4*>(
                        srcb + (size_t)row * DFEAT + k0) + c8);
                soff = (isLo ? B_LO_OFF : B_HI_OFF) + (uint32_t)row * ROWB + c8 * 16;
            }
            *reinterpret_cast<uint4*>(smem + soff) = v;
        }
        __syncthreads();

#pragma unroll
        for (int ks = 0; ks < 4; ks++) {
            int kk = ks * 16;

            uint32_t a_hi[2][4], a_lo[2][4];
#pragma unroll
            for (int mt = 0; mt < 2; mt++) {
                int m = wm * 32 + mt * 16 + (lane & 15);
                uint32_t byteoff = (uint32_t)m * ROWB +
                                   (uint32_t)(kk + (lane >> 4) * 8) * 2;
                LDSM_X4(a_hi[mt][0], a_hi[mt][1], a_hi[mt][2], a_hi[mt][3],
                        sb + A_HI_OFF + byteoff);
                LDSM_X4(a_lo[mt][0], a_lo[mt][1], a_lo[mt][2], a_lo[mt][3],
                        sb + A_LO_OFF + byteoff);
            }

#pragma unroll
            for (int ng = 0; ng < 4; ng++) {
                int g = lane >> 3;
                int n = wn * 64 + ng * 16 + (g >> 1) * 8 + (lane & 7);
                uint32_t byteoff = (uint32_t)n * ROWB +
                                   (uint32_t)(kk + (g & 1) * 8) * 2;
                uint32_t b_hi[4], b_lo[4];
                LDSM_X4(b_hi[0], b_hi[1], b_hi[2], b_hi[3], sb + B_HI_OFF + byteoff);
                LDSM_X4(b_lo[0], b_lo[1], b_lo[2], b_lo[3], sb + B_LO_OFF + byteoff);
#pragma unroll
                for (int mt = 0; mt < 2; mt++) {
#pragma unroll
                    for (int h = 0; h < 2; h++) {
                        int nt = ng * 2 + h;
                        MMA_BF16(acc[mt][nt], a_hi[mt], b_hi[h * 2], b_hi[h * 2 + 1]);
                        MMA_BF16(acc[mt][nt], a_hi[mt], b_lo[h * 2], b_lo[h * 2 + 1]);
                        MMA_BF16(acc[mt][nt], a_lo[mt], b_hi[h * 2], b_hi[h * 2 + 1]);
                    }
                }
            }
        }
        __syncthreads();
    }

#pragma unroll
    for (int mt = 0; mt < 2; mt++) {
        int r0 = blockRow + wm * 32 + mt * 16 + (lane >> 2);
        int r1 = r0 + 8;
#pragma unroll
        for (int nt = 0; nt < 8; nt++) {
            int cb = wn * 64 + nt * 8 + (lane & 3) * 2;
            float2 bb = *reinterpret_cast<const float2*>(bias + cb);
            float2 o0, o1;
            o0.x = acc[mt][nt][0] + bb.x;
            o0.y = acc[mt][nt][1] + bb.y;
            o1.x = acc[mt][nt][2] + bb.x;
            o1.y = acc[mt][nt][3] + bb.y;
            *reinterpret_cast<float2*>(out + (size_t)r0 * 128 + cb) = o0;
            *reinterpret_cast<float2*>(out + (size_t)r1 * 128 + cb) = o1;
        }
    }
}

// ---------------------------------------------------------------------------
extern "C" void kernel_launch(void* const* d_in, const int* in_sizes, int n_in,
                              void* d_out, int out_size) {
    const float* ndata = (const float*)d_in[0];
    const int*   src   = (const int*)d_in[1];
    const int*   dst   = (const int*)d_in[2];
    const float* W     = (const float*)d_in[3];
    const float* b     = (const float*)d_in[4];
    float* out = (float*)d_out;

    (void)in_sizes; (void)n_in; (void)out_size;

    cudaFuncSetAttribute(k_gemm_mma, cudaFuncAttributeMaxDynamicSharedMemorySize,
                         SMEM_GEMM);

    k_init<<<(N_NODES + 255) / 256, 256>>>(W);
    k_deg<<<(N_EDGES / 4 + 255) / 256, 256>>>(dst);
    k_scan1<<<SCAN_BLOCKS, 1024>>>();
    k_scan2<<<1, 64>>>();
    k_scan3<<<SCAN_BLOCKS, 1024>>>();
    k_fill<<<(N_EDGES / 4 + 255) / 256, 256>>>(src, dst);
    {
        long long threads = (long long)N_NODES * 32;
        int blocks = (int)((threads + 255) / 256);
        k_gather<<<blocks, 256>>>(ndata);
    }
    k_gemm_mma<<<250, 320, SMEM_GEMM>>>(b, out);
}

// round 13
// speedup vs baseline: 3.4417x; 1.0217x over previous
#include <cuda_runtime.h>
#include <cuda_bf16.h>
#include <cuda_fp16.h>
#include <cstdint>

#define N_NODES 40000
#define DFEAT   128
#define N_EDGES 640000
#define SCAN_BLOCKS 40            // 40*1024 = 40960 >= 40000

// Scratch (static device globals — no allocation)
__device__ int   g_deg[N_NODES];
__device__ int   g_off[N_NODES + 1];        // CSR row offsets
__device__ int   g_rank[N_EDGES];           // per-edge rank within dst node
__device__ int   g_csrc[N_EDGES];           // CSR-ordered source indices
__device__ int   g_bsum[SCAN_BLOCKS];       // scan block totals
__device__ int   g_cnt;                     // scan grid-barrier counter
__device__ __half        g_nh[N_NODES * DFEAT];   // ndata fp16 (neighbor cache)
__device__ __nv_bfloat16 g_hh[N_NODES * DFEAT];   // h hi (bf16)
__device__ __nv_bfloat16 g_hl[N_NODES * DFEAT];   // h lo (bf16)
__device__ __nv_bfloat16 g_wh[DFEAT * DFEAT];     // W hi
__device__ __nv_bfloat16 g_wl[DFEAT * DFEAT];     // W lo

// ===========================================================================
// PTX helpers — baseline PTX only (sm_80+ mma.sync / sm_75+ ldmatrix).
// ===========================================================================
__device__ __forceinline__ uint32_t smem_u32(const void* p) {
    uint32_t a;
    asm("{ .reg .u64 t; cvta.to.shared.u64 t, %1; cvt.u32.u64 %0, t; }"
        : "=r"(a) : "l"(p));
    return a;
}

#define LDSM_X4(r0, r1, r2, r3, addr) \
    asm volatile("ldmatrix.sync.aligned.m8n8.x4.shared.b16 {%0,%1,%2,%3}, [%4];" \
                 : "=r"(r0), "=r"(r1), "=r"(r2), "=r"(r3) : "r"(addr))

#define MMA_BF16(c, a, b0, b1) \
    asm volatile("mma.sync.aligned.m16n8k16.row.col.f32.bf16.bf16.f32 " \
                 "{%0,%1,%2,%3}, {%4,%5,%6,%7}, {%8,%9}, {%0,%1,%2,%3};" \
                 : "+f"((c)[0]), "+f"((c)[1]), "+f"((c)[2]), "+f"((c)[3]) \
                 : "r"((a)[0]), "r"((a)[1]), "r"((a)[2]), "r"((a)[3]), \
                   "r"(b0), "r"(b1))

__device__ __forceinline__ uint32_t pack_hi2(float x, float y,
                                             float& rx, float& ry) {
    __nv_bfloat16 hx = __float2bfloat16(x);
    __nv_bfloat16 hy = __float2bfloat16(y);
    rx = x - __bfloat162float(hx);
    ry = y - __bfloat162float(hy);
    return ((uint32_t)__bfloat16_as_ushort(hy) << 16) | __bfloat16_as_ushort(hx);
}
__device__ __forceinline__ uint32_t pack_lo2(float rx, float ry) {
    __nv_bfloat16 lx = __float2bfloat16(rx);
    __nv_bfloat16 ly = __float2bfloat16(ry);
    return ((uint32_t)__bfloat16_as_ushort(ly) << 16) | __bfloat16_as_ushort(lx);
}

// ===========================================================================
// k_init: fused  W bf16 hi/lo split  +  deg=0  +  barrier reset  +
//         ndata fp32 -> fp16 neighbor cache
// grid covers N_NODES*DFEAT/4 = 1,280,000 float4 items.
// ===========================================================================
__global__ void k_init(const float* __restrict__ ndata,
                       const float* __restrict__ W) {
    int i = blockIdx.x * blockDim.x + threadIdx.x;
    if (i == 0) g_cnt = 0;
    if (i < DFEAT * DFEAT / 4) {
        float4 v = __ldg(reinterpret_cast<const float4*>(W) + i);
        float r0, r1, r2, r3;
        uint32_t hiA = pack_hi2(v.x, v.y, r0, r1);
        uint32_t hiB = pack_hi2(v.z, v.w, r2, r3);
        uint32_t loA = pack_lo2(r0, r1);
        uint32_t loB = pack_lo2(r2, r3);
        reinterpret_cast<uint2*>(g_wh)[i] = make_uint2(hiA, hiB);
        reinterpret_cast<uint2*>(g_wl)[i] = make_uint2(loA, loB);
    }
    if (i < N_NODES) g_deg[i] = 0;
    if (i < N_NODES * DFEAT / 4) {
        float4 v = __ldg(reinterpret_cast<const float4*>(ndata) + i);
        __half2 a = __floats2half2_rn(v.x, v.y);
        __half2 b = __floats2half2_rn(v.z, v.w);
        uint2 o;
        o.x = *reinterpret_cast<uint32_t*>(&a);
        o.y = *reinterpret_cast<uint32_t*>(&b);
        reinterpret_cast<uint2*>(g_nh)[i] = o;
    }
}

// ===========================================================================
// k_deg: in-degree histogram + per-edge rank capture (single atomic pass)
// ===========================================================================
__global__ void k_deg(const int* __restrict__ dst) {
    int t = blockIdx.x * blockDim.x + threadIdx.x;   // over groups of 4
    if (t < N_EDGES / 4) {
        int4 d = __ldg(reinterpret_cast<const int4*>(dst) + t);
        int4 r;
        r.x = atomicAdd(&g_deg[d.x], 1);
        r.y = atomicAdd(&g_deg[d.y], 1);
        r.z = atomicAdd(&g_deg[d.z], 1);
        r.w = atomicAdd(&g_deg[d.w], 1);
        reinterpret_cast<int4*>(g_rank)[t] = r;
    }
}

// ===========================================================================
// k_scan: single-kernel exclusive scan over 40000 degrees.
// 40 co-resident blocks (<= 148 SMs, guaranteed wave-1) + software grid
// barrier on g_cnt (reset in k_init each call -> deterministic).
// ===========================================================================
__global__ __launch_bounds__(1024) void k_scan() {
    __shared__ int sh[1024];
    __shared__ int s_bpre;
    int b = blockIdx.x, tid = threadIdx.x;
    int i = b * 1024 + tid;
    int v = (i < N_NODES) ? g_deg[i] : 0;
    int val = v;
    sh[tid] = val;
    __syncthreads();
    for (int s = 1; s < 1024; s <<= 1) {
        int o = (tid >= s) ? sh[tid - s] : 0;
        __syncthreads();
        val += o;
        sh[tid] = val;
        __syncthreads();
    }
    // publish block total, arrive at grid barrier
    if (tid == 1023) {
        g_bsum[b] = val;
        __threadfence();
        atomicAdd(&g_cnt, 1);
    }
    if (tid == 0) {
        while (atomicAdd(&g_cnt, 0) < SCAN_BLOCKS) { }
    }
    __syncthreads();
    // gather all block totals (atomic reads bypass L1; parallel latency)
    if (tid < SCAN_BLOCKS) sh[tid] = atomicAdd(&g_bsum[tid], 0);
    __syncthreads();
    if (tid == 0) {
        int p = 0;
        for (int j = 0; j < b; j++) p += sh[j];
        s_bpre = p;
        if (b == SCAN_BLOCKS - 1) g_off[N_NODES] = p + sh[SCAN_BLOCKS - 1];
    }
    __syncthreads();
    if (i < N_NODES) g_off[i] = (val - v) + s_bpre;
}

// ===========================================================================
// k_fill: atomic-free scatter — position = g_off[dst] + rank
// ===========================================================================
__global__ void k_fill(const int* __restrict__ src,
                       const int* __restrict__ dst) {
    int t = blockIdx.x * blockDim.x + threadIdx.x;   // over groups of 4
    if (t < N_EDGES / 4) {
        int4 d = __ldg(reinterpret_cast<const int4*>(dst) + t);
        int4 s = __ldg(reinterpret_cast<const int4*>(src) + t);
        int4 r = __ldg(reinterpret_cast<const int4*>(g_rank) + t);
        g_csrc[__ldg(&g_off[d.x]) + r.x] = s.x;
        g_csrc[__ldg(&g_off[d.y]) + r.y] = s.y;
        g_csrc[__ldg(&g_off[d.z]) + r.z] = s.z;
        g_csrc[__ldg(&g_off[d.w]) + r.w] = s.w;
    }
}

// ===========================================================================
// k_gather: one warp per node; fp16 neighbor reads, fp32 self + accumulation;
// emits bf16 hi/lo of h.
// ===========================================================================
__device__ __forceinline__ void add_half4(float4& acc, uint2 p) {
    float2 a = __half22float2(*reinterpret_cast<__half2*>(&p.x));
    float2 b = __half22float2(*reinterpret_cast<__half2*>(&p.y));
    acc.x += a.x; acc.y += a.y; acc.z += b.x; acc.w += b.y;
}

__global__ __launch_bounds__(256) void k_gather(const float* __restrict__ ndata) {
    int gt   = blockIdx.x * blockDim.x + threadIdx.x;
    int v    = gt >> 5;
    int lane = gt & 31;
    if (v >= N_NODES) return;

    int off0 = g_off[v];
    int off1 = g_off[v + 1];
    int d    = off1 - off0;
    float inv = 1.0f / (float)(d > 0 ? d : 1);

    const uint2* nh = reinterpret_cast<const uint2*>(g_nh);   // row stride 32

    float4 acc = make_float4(0.f, 0.f, 0.f, 0.f);

    int i = off0;
    for (; i + 4 <= off1; i += 4) {
        int s0 = __ldg(g_csrc + i);
        int s1 = __ldg(g_csrc + i + 1);
        int s2 = __ldg(g_csrc + i + 2);
        int s3 = __ldg(g_csrc + i + 3);
        uint2 p0 = __ldg(nh + (size_t)s0 * 32 + lane);
        uint2 p1 = __ldg(nh + (size_t)s1 * 32 + lane);
        uint2 p2 = __ldg(nh + (size_t)s2 * 32 + lane);
        uint2 p3 = __ldg(nh + (size_t)s3 * 32 + lane);
        add_half4(acc, p0);
        add_half4(acc, p1);
        add_half4(acc, p2);
        add_half4(acc, p3);
    }
    for (; i < off1; i++) {
        int s = __ldg(g_csrc + i);
        uint2 p = __ldg(nh + (size_t)s * 32 + lane);
        add_half4(acc, p);
    }

    float4 self = __ldg(reinterpret_cast<const float4*>(ndata + (size_t)v * DFEAT) + lane);
    float4 h;
    h.x = self.x + acc.x * inv;
    h.y = self.y + acc.y * inv;
    h.z = self.z + acc.z * inv;
    h.w = self.w + acc.w * inv;

    float r0, r1, r2, r3;
    uint32_t hiA = pack_hi2(h.x, h.y, r0, r1);
    uint32_t hiB = pack_hi2(h.z, h.w, r2, r3);
    uint32_t loA = pack_lo2(r0, r1);
    uint32_t loB = pack_lo2(r2, r3);

    size_t o = (size_t)v * DFEAT / 4 + lane;   // uint2 index
    reinterpret_cast<uint2*>(g_hh)[o] = make_uint2(hiA, hiB);
    reinterpret_cast<uint2*>(g_hl)[o] = make_uint2(loA, loB);
}

// ===========================================================================
// k_gemm_mma: out[40000,128] = h @ W^T + b  (bf16 split, 3 terms, fp32 accum)
// BM=160, BN=128; grid 250; 320 threads = 10 warps (5 M x 2 N).
// ===========================================================================
#define TSTRIDE   72
#define ROWB      (TSTRIDE * 2)                 // 144 B per row
#define A_HI_OFF  0
#define A_LO_OFF  (160 * ROWB)                  // 23040
#define B_HI_OFF  (2 * 160 * ROWB)              // 46080
#define B_LO_OFF  (B_HI_OFF + 128 * ROWB)       // 64512
#define SMEM_GEMM (B_LO_OFF + 128 * ROWB)       // 82944

__global__ __launch_bounds__(320, 2) void k_gemm_mma(const float* __restrict__ bias,
                                                     float* __restrict__ out) {
    extern __shared__ char smem[];
    uint32_t sb = smem_u32(smem);
    int tid  = threadIdx.x;
    int wid  = tid >> 5;
    int lane = tid & 31;
    int wm = wid % 5;
    int wn = wid / 5;
    int blockRow = blockIdx.x * 160;

    float acc[2][8][4];
#pragma unroll
    for (int mt = 0; mt < 2; mt++)
#pragma unroll
        for (int nt = 0; nt < 8; nt++)
#pragma unroll
            for (int c = 0; c < 4; c++) acc[mt][nt][c] = 0.0f;

    for (int r = 0; r < 2; r++) {
        int k0 = r * 64;

        for (int idx = tid; idx < 4608; idx += 320) {
            uint4 v;
            uint32_t soff;
            if (idx < 2560) {
                int isLo = idx >= 1280;
                int q    = isLo ? idx - 1280 : idx;
                int row  = q >> 3;
                int c8   = q & 7;
                const __nv_bfloat16* srcb = isLo ? g_hl : g_hh;
                v = __ldg(reinterpret_cast<const uint4*>(
                        srcb + (size_t)(blockRow + row) * DFEAT + k0) + c8);
                soff = (isLo ? A_LO_OFF : A_HI_OFF) + (uint32_t)row * ROWB + c8 * 16;
            } else {
                int q2   = idx - 2560;
                int isLo = q2 >= 1024;
                int q    = isLo ? q2 - 1024 : q2;
                int row  = q >> 3;
                int c8   = q & 7;
                const __nv_bfloat16* srcb = isLo ? g_wl : g_wh;
                v = __ldg(reinterpret_cast<const uint4*>(
                        srcb + (size_t)row * DFEAT + k0) + c8);
                soff = (isLo ? B_LO_OFF : B_HI_OFF) + (uint32_t)row * ROWB + c8 * 16;
            }
            *reinterpret_cast<uint4*>(smem + soff) = v;
        }
        __syncthreads();

#pragma unroll
        for (int ks = 0; ks < 4; ks++) {
            int kk = ks * 16;

            uint32_t a_hi[2][4], a_lo[2][4];
#pragma unroll
            for (int mt = 0; mt < 2; mt++) {
                int m = wm * 32 + mt * 16 + (lane & 15);
                uint32_t byteoff = (uint32_t)m * ROWB +
                                   (uint32_t)(kk + (lane >> 4) * 8) * 2;
                LDSM_X4(a_hi[mt][0], a_hi[mt][1], a_hi[mt][2], a_hi[mt][3],
                        sb + A_HI_OFF + byteoff);
                LDSM_X4(a_lo[mt][0], a_lo[mt][1], a_lo[mt][2], a_lo[mt][3],
                        sb + A_LO_OFF + byteoff);
            }

#pragma unroll
            for (int ng = 0; ng < 4; ng++) {
                int g = lane >> 3;
                int n = wn * 64 + ng * 16 + (g >> 1) * 8 + (lane & 7);
                uint32_t byteoff = (uint32_t)n * ROWB +
                                   (uint32_t)(kk + (g & 1) * 8) * 2;
                uint32_t b_hi[4], b_lo[4];
                LDSM_X4(b_hi[0], b_hi[1], b_hi[2], b_hi[3], sb + B_HI_OFF + byteoff);
                LDSM_X4(b_lo[0], b_lo[1], b_lo[2], b_lo[3], sb + B_LO_OFF + byteoff);
#pragma unroll
                for (int mt = 0; mt < 2; mt++) {
#pragma unroll
                    for (int h = 0; h < 2; h++) {
                        int nt = ng * 2 + h;
                        MMA_BF16(acc[mt][nt], a_hi[mt], b_hi[h * 2], b_hi[h * 2 + 1]);
                        MMA_BF16(acc[mt][nt], a_hi[mt], b_lo[h * 2], b_lo[h * 2 + 1]);
                        MMA_BF16(acc[mt][nt], a_lo[mt], b_hi[h * 2], b_hi[h * 2 + 1]);
                    }
                }
            }
        }
        __syncthreads();
    }

#pragma unroll
    for (int mt = 0; mt < 2; mt++) {
        int r0 = blockRow + wm * 32 + mt * 16 + (lane >> 2);
        int r1 = r0 + 8;
#pragma unroll
        for (int nt = 0; nt < 8; nt++) {
            int cb = wn * 64 + nt * 8 + (lane & 3) * 2;
            float2 bb = *reinterpret_cast<const float2*>(bias + cb);
            float2 o0, o1;
            o0.x = acc[mt][nt][0] + bb.x;
            o0.y = acc[mt][nt][1] + bb.y;
            o1.x = acc[mt][nt][2] + bb.x;
            o1.y = acc[mt][nt][3] + bb.y;
            *reinterpret_cast<float2*>(out + (size_t)r0 * 128 + cb) = o0;
            *reinterpret_cast<float2*>(out + (size_t)r1 * 128 + cb) = o1;
        }
    }
}

// ---------------------------------------------------------------------------
extern "C" void kernel_launch(void* const* d_in, const int* in_sizes, int n_in,
                              void* d_out, int out_size) {
    const float* ndata = (const float*)d_in[0];
    const int*   src   = (const int*)d_in[1];
    const int*   dst   = (const int*)d_in[2];
    const float* W     = (const float*)d_in[3];
    const float* b     = (const float*)d_in[4];
    float* out = (float*)d_out;

    (void)in_sizes; (void)n_in; (void)out_size;

    cudaFuncSetAttribute(k_gemm_mma, cudaFuncAttributeMaxDynamicSharedMemorySize,
                         SMEM_GEMM);

    k_init<<<(N_NODES * DFEAT / 4 + 255) / 256, 256>>>(ndata, W);
    k_deg<<<(N_EDGES / 4 + 255) / 256, 256>>>(dst);
    k_scan<<<SCAN_BLOCKS, 1024>>>();
    k_fill<<<(N_EDGES / 4 + 255) / 256, 256>>>(src, dst);
    {
        long long threads = (long long)N_NODES * 32;
        int blocks = (int)((threads + 255) / 256);
        k_gather<<<blocks, 256>>>(ndata);
    }
    k_gemm_mma<<<250, 320, SMEM_GEMM>>>(b, out);
}

// round 14
// speedup vs baseline: 3.5666x; 1.0363x over previous
#include <cuda_runtime.h>
#include <cuda_bf16.h>
#include <cuda_fp16.h>
#include <cstdint>

#define N_NODES 40000
#define DFEAT   128
#define N_EDGES 640000
#define SCAN_BLOCKS 40            // 40*1024 = 40960 >= 40000

// Scratch (static device globals — no allocation). Zero-initialized at load;
// g_deg / g_cnt are re-zeroed by k_fill each call so every graph replay sees
// identical state.
__device__ int   g_deg[N_NODES];
__device__ int   g_off[N_NODES + 1];        // CSR row offsets
__device__ int   g_rank[N_EDGES];           // per-edge rank within dst node
__device__ int   g_csrc[N_EDGES];           // CSR-ordered source indices
__device__ int   g_bsum[SCAN_BLOCKS];       // scan block totals
__device__ int   g_cnt;                     // scan grid-barrier counter
__device__ __half        g_nh[N_NODES * DFEAT];   // ndata fp16 (neighbor cache)
__device__ __nv_bfloat16 g_hh[N_NODES * DFEAT];   // h hi (bf16)
__device__ __nv_bfloat16 g_hl[N_NODES * DFEAT];   // h lo (bf16)
__device__ __nv_bfloat16 g_wh[DFEAT * DFEAT];     // W hi
__device__ __nv_bfloat16 g_wl[DFEAT * DFEAT];     // W lo

// ===========================================================================
// PTX helpers — baseline PTX only (sm_80+ mma.sync / sm_75+ ldmatrix).
// ===========================================================================
__device__ __forceinline__ uint32_t smem_u32(const void* p) {
    uint32_t a;
    asm("{ .reg .u64 t; cvta.to.shared.u64 t, %1; cvt.u32.u64 %0, t; }"
        : "=r"(a) : "l"(p));
    return a;
}

#define LDSM_X4(r0, r1, r2, r3, addr) \
    asm volatile("ldmatrix.sync.aligned.m8n8.x4.shared.b16 {%0,%1,%2,%3}, [%4];" \
                 : "=r"(r0), "=r"(r1), "=r"(r2), "=r"(r3) : "r"(addr))

#define MMA_BF16(c, a, b0, b1) \
    asm volatile("mma.sync.aligned.m16n8k16.row.col.f32.bf16.bf16.f32 " \
                 "{%0,%1,%2,%3}, {%4,%5,%6,%7}, {%8,%9}, {%0,%1,%2,%3};" \
                 : "+f"((c)[0]), "+f"((c)[1]), "+f"((c)[2]), "+f"((c)[3]) \
                 : "r"((a)[0]), "r"((a)[1]), "r"((a)[2]), "r"((a)[3]), \
                   "r"(b0), "r"(b1))

__device__ __forceinline__ uint32_t pack_hi2(float x, float y,
                                             float& rx, float& ry) {
    __nv_bfloat16 hx = __float2bfloat16(x);
    __nv_bfloat16 hy = __float2bfloat16(y);
    rx = x - __bfloat162float(hx);
    ry = y - __bfloat162float(hy);
    return ((uint32_t)__bfloat16_as_ushort(hy) << 16) | __bfloat16_as_ushort(hx);
}
__device__ __forceinline__ uint32_t pack_lo2(float rx, float ry) {
    __nv_bfloat16 lx = __float2bfloat16(rx);
    __nv_bfloat16 ly = __float2bfloat16(ry);
    return ((uint32_t)__bfloat16_as_ushort(ly) << 16) | __bfloat16_as_ushort(lx);
}

// ===========================================================================
// k_head: FUSED  deg histogram + rank capture  ∥  ndata fp32->fp16 convert
//         ∥  W bf16 hi/lo split.
// Edge atomics (latency-bound, first 625 blocks) overlap the conversion
// stream (bandwidth-bound, remaining blocks). g_deg==0 at entry is an
// invariant: zero-init at load + k_fill re-zeros each call.
// ===========================================================================
__global__ void k_head(const float* __restrict__ ndata,
                       const float* __restrict__ W,
                       const int* __restrict__ dst) {
    int i = blockIdx.x * blockDim.x + threadIdx.x;

    if (i < N_EDGES / 4) {                      // deg + rank (groups of 4)
        int4 d = __ldg(reinterpret_cast<const int4*>(dst) + i);
        int4 r;
        r.x = atomicAdd(&g_deg[d.x], 1);
        r.y = atomicAdd(&g_deg[d.y], 1);
        r.z = atomicAdd(&g_deg[d.z], 1);
        r.w = atomicAdd(&g_deg[d.w], 1);
        reinterpret_cast<int4*>(g_rank)[i] = r;
    }
    if (i < DFEAT * DFEAT / 4) {                // W split
        float4 v = __ldg(reinterpret_cast<const float4*>(W) + i);
        float r0, r1, r2, r3;
        uint32_t hiA = pack_hi2(v.x, v.y, r0, r1);
        uint32_t hiB = pack_hi2(v.z, v.w, r2, r3);
        uint32_t loA = pack_lo2(r0, r1);
        uint32_t loB = pack_lo2(r2, r3);
        reinterpret_cast<uint2*>(g_wh)[i] = make_uint2(hiA, hiB);
        reinterpret_cast<uint2*>(g_wl)[i] = make_uint2(loA, loB);
    }
    if (i < N_NODES * DFEAT / 4) {              // fp16 neighbor cache
        float4 v = __ldg(reinterpret_cast<const float4*>(ndata) + i);
        __half2 a = __floats2half2_rn(v.x, v.y);
        __half2 b = __floats2half2_rn(v.z, v.w);
        uint2 o;
        o.x = *reinterpret_cast<uint32_t*>(&a);
        o.y = *reinterpret_cast<uint32_t*>(&b);
        reinterpret_cast<uint2*>(g_nh)[i] = o;
    }
}

// ===========================================================================
// k_scan: single-kernel exclusive scan over 40000 degrees.
// 40 co-resident blocks + software grid barrier on g_cnt.
// ===========================================================================
__global__ __launch_bounds__(1024) void k_scan() {
    __shared__ int sh[1024];
    __shared__ int s_bpre;
    int b = blockIdx.x, tid = threadIdx.x;
    int i = b * 1024 + tid;
    int v = (i < N_NODES) ? g_deg[i] : 0;
    int val = v;
    sh[tid] = val;
    __syncthreads();
    for (int s = 1; s < 1024; s <<= 1) {
        int o = (tid >= s) ? sh[tid - s] : 0;
        __syncthreads();
        val += o;
        sh[tid] = val;
        __syncthreads();
    }
    if (tid == 1023) {
        g_bsum[b] = val;
        __threadfence();
        atomicAdd(&g_cnt, 1);
    }
    if (tid == 0) {
        while (atomicAdd(&g_cnt, 0) < SCAN_BLOCKS) { }
    }
    __syncthreads();
    if (tid < SCAN_BLOCKS) sh[tid] = atomicAdd(&g_bsum[tid], 0);
    __syncthreads();
    if (tid == 0) {
        int p = 0;
        for (int j = 0; j < b; j++) p += sh[j];
        s_bpre = p;
        if (b == SCAN_BLOCKS - 1) g_off[N_NODES] = p + sh[SCAN_BLOCKS - 1];
    }
    __syncthreads();
    if (i < N_NODES) g_off[i] = (val - v) + s_bpre;
}

// ===========================================================================
// k_fill: atomic-free scatter — position = g_off[dst] + rank.
// x8 edge batching (2x int4 streams) for memory-level parallelism.
// Also re-zeros g_deg and g_cnt for the next graph replay.
// ===========================================================================
__global__ void k_fill(const int* __restrict__ src,
                       const int* __restrict__ dst) {
    int t = blockIdx.x * blockDim.x + threadIdx.x;   // over groups of 8
    if (t < N_EDGES / 8) {
        const int4* d4 = reinterpret_cast<const int4*>(dst) + t * 2;
        const int4* s4 = reinterpret_cast<const int4*>(src) + t * 2;
        const int4* r4 = reinterpret_cast<const int4*>(g_rank) + t * 2;
        int4 d0 = __ldg(d4);
        int4 d1 = __ldg(d4 + 1);
        int4 s0 = __ldg(s4);
        int4 s1 = __ldg(s4 + 1);
        int4 r0 = __ldg(r4);
        int4 r1 = __ldg(r4 + 1);
        int o0 = __ldg(&g_off[d0.x]);
        int o1 = __ldg(&g_off[d0.y]);
        int o2 = __ldg(&g_off[d0.z]);
        int o3 = __ldg(&g_off[d0.w]);
        int o4 = __ldg(&g_off[d1.x]);
        int o5 = __ldg(&g_off[d1.y]);
        int o6 = __ldg(&g_off[d1.z]);
        int o7 = __ldg(&g_off[d1.w]);
        g_csrc[o0 + r0.x] = s0.x;
        g_csrc[o1 + r0.y] = s0.y;
        g_csrc[o2 + r0.z] = s0.z;
        g_csrc[o3 + r0.w] = s0.w;
        g_csrc[o4 + r1.x] = s1.x;
        g_csrc[o5 + r1.y] = s1.y;
        g_csrc[o6 + r1.z] = s1.z;
        g_csrc[o7 + r1.w] = s1.w;
    }
    if (t < N_NODES) g_deg[t] = 0;     // reset for next replay (80K threads >= 40K)
    if (t == 0) g_cnt = 0;
}

// ===========================================================================
// k_gather: one warp per node; fp16 neighbor reads, fp32 self + accumulation;
// emits bf16 hi/lo of h.
// ===========================================================================
__device__ __forceinline__ void add_half4(float4& acc, uint2 p) {
    float2 a = __half22float2(*reinterpret_cast<__half2*>(&p.x));
    float2 b = __half22float2(*reinterpret_cast<__half2*>(&p.y));
    acc.x += a.x; acc.y += a.y; acc.z += b.x; acc.w += b.y;
}

__global__ __launch_bounds__(256) void k_gather(const float* __restrict__ ndata) {
    int gt   = blockIdx.x * blockDim.x + threadIdx.x;
    int v    = gt >> 5;
    int lane = gt & 31;
    if (v >= N_NODES) return;

    int off0 = g_off[v];
    int off1 = g_off[v + 1];
    int d    = off1 - off0;
    float inv = 1.0f / (float)(d > 0 ? d : 1);

    const uint2* nh = reinterpret_cast<const uint2*>(g_nh);   // row stride 32

    float4 acc = make_float4(0.f, 0.f, 0.f, 0.f);

    int i = off0;
    for (; i + 4 <= off1; i += 4) {
        int s0 = __ldg(g_csrc + i);
        int s1 = __ldg(g_csrc + i + 1);
        int s2 = __ldg(g_csrc + i + 2);
        int s3 = __ldg(g_csrc + i + 3);
        uint2 p0 = __ldg(nh + (size_t)s0 * 32 + lane);
        uint2 p1 = __ldg(nh + (size_t)s1 * 32 + lane);
        uint2 p2 = __ldg(nh + (size_t)s2 * 32 + lane);
        uint2 p3 = __ldg(nh + (size_t)s3 * 32 + lane);
        add_half4(acc, p0);
        add_half4(acc, p1);
        add_half4(acc, p2);
        add_half4(acc, p3);
    }
    for (; i < off1; i++) {
        int s = __ldg(g_csrc + i);
        uint2 p = __ldg(nh + (size_t)s * 32 + lane);
        add_half4(acc, p);
    }

    float4 self = __ldg(reinterpret_cast<const float4*>(ndata + (size_t)v * DFEAT) + lane);
    float4 h;
    h.x = self.x + acc.x * inv;
    h.y = self.y + acc.y * inv;
    h.z = self.z + acc.z * inv;
    h.w = self.w + acc.w * inv;

    float r0, r1, r2, r3;
    uint32_t hiA = pack_hi2(h.x, h.y, r0, r1);
    uint32_t hiB = pack_hi2(h.z, h.w, r2, r3);
    uint32_t loA = pack_lo2(r0, r1);
    uint32_t loB = pack_lo2(r2, r3);

    size_t o = (size_t)v * DFEAT / 4 + lane;   // uint2 index
    reinterpret_cast<uint2*>(g_hh)[o] = make_uint2(hiA, hiB);
    reinterpret_cast<uint2*>(g_hl)[o] = make_uint2(loA, loB);
}

// ===========================================================================
// k_gemm_mma: out[40000,128] = h @ W^T + b  (bf16 split, 3 terms, fp32 accum)
// BM=160, BN=128; grid 250; 320 threads = 10 warps (5 M x 2 N).
// ===========================================================================
#define TSTRIDE   72
#define ROWB      (TSTRIDE * 2)                 // 144 B per row
#define A_HI_OFF  0
#define A_LO_OFF  (160 * ROWB)                  // 23040
#define B_HI_OFF  (2 * 160 * ROWB)              // 46080
#define B_LO_OFF  (B_HI_OFF + 128 * ROWB)       // 64512
#define SMEM_GEMM (B_LO_OFF + 128 * ROWB)       // 82944

__global__ __launch_bounds__(320, 2) void k_gemm_mma(const float* __restrict__ bias,
                                                     float* __restrict__ out) {
    extern __shared__ char smem[];
    uint32_t sb = smem_u32(smem);
    int tid  = threadIdx.x;
    int wid  = tid >> 5;
    int lane = tid & 31;
    int wm = wid % 5;
    int wn = wid / 5;
    int blockRow = blockIdx.x * 160;

    float acc[2][8][4];
#pragma unroll
    for (int mt = 0; mt < 2; mt++)
#pragma unroll
        for (int nt = 0; nt < 8; nt++)
#pragma unroll
            for (int c = 0; c < 4; c++) acc[mt][nt][c] = 0.0f;

    for (int r = 0; r < 2; r++) {
        int k0 = r * 64;

        for (int idx = tid; idx < 4608; idx += 320) {
            uint4 v;
            uint32_t soff;
            if (idx < 2560) {
                int isLo = idx >= 1280;
                int q    = isLo ? idx - 1280 : idx;
                int row  = q >> 3;
                int c8   = q & 7;
                const __nv_bfloat16* srcb = isLo ? g_hl : g_hh;
                v = __ldg(reinterpret_cast<const uint4*>(
                        srcb + (size_t)(blockRow + row) * DFEAT + k0) + c8);
                soff = (isLo ? A_LO_OFF : A_HI_OFF) + (uint32_t)row * ROWB + c8 * 16;
            } else {
                int q2   = idx - 2560;
                int isLo = q2 >= 1024;
                int q    = isLo ? q2 - 1024 : q2;
                int row  = q >> 3;
                int c8   = q & 7;
                const __nv_bfloat16* srcb = isLo ? g_wl : g_wh;
                v = __ldg(reinterpret_cast<const uint4*>(
                        srcb + (size_t)row * DFEAT + k0) + c8);
                soff = (isLo ? B_LO_OFF : B_HI_OFF) + (uint32_t)row * ROWB + c8 * 16;
            }
            *reinterpret_cast<uint4*>(smem + soff) = v;
        }
        __syncthreads();

#pragma unroll
        for (int ks = 0; ks < 4; ks++) {
            int kk = ks * 16;

            uint32_t a_hi[2][4], a_lo[2][4];
#pragma unroll
            for (int mt = 0; mt < 2; mt++) {
                int m = wm * 32 + mt * 16 + (lane & 15);
                uint32_t byteoff = (uint32_t)m * ROWB +
                                   (uint32_t)(kk + (lane >> 4) * 8) * 2;
                LDSM_X4(a_hi[mt][0], a_hi[mt][1], a_hi[mt][2], a_hi[mt][3],
                        sb + A_HI_OFF + byteoff);
                LDSM_X4(a_lo[mt][0], a_lo[mt][1], a_lo[mt][2], a_lo[mt][3],
                        sb + A_LO_OFF + byteoff);
            }

#pragma unroll
            for (int ng = 0; ng < 4; ng++) {
                int g = lane >> 3;
                int n = wn * 64 + ng * 16 + (g >> 1) * 8 + (lane & 7);
                uint32_t byteoff = (uint32_t)n * ROWB +
                                   (uint32_t)(kk + (g & 1) * 8) * 2;
                uint32_t b_hi[4], b_lo[4];
                LDSM_X4(b_hi[0], b_hi[1], b_hi[2], b_hi[3], sb + B_HI_OFF + byteoff);
                LDSM_X4(b_lo[0], b_lo[1], b_lo[2], b_lo[3], sb + B_LO_OFF + byteoff);
#pragma unroll
                for (int mt = 0; mt < 2; mt++) {
#pragma unroll
                    for (int h = 0; h < 2; h++) {
                        int nt = ng * 2 + h;
                        MMA_BF16(acc[mt][nt], a_hi[mt], b_hi[h * 2], b_hi[h * 2 + 1]);
                        MMA_BF16(acc[mt][nt], a_hi[mt], b_lo[h * 2], b_lo[h * 2 + 1]);
                        MMA_BF16(acc[mt][nt], a_lo[mt], b_hi[h * 2], b_hi[h * 2 + 1]);
                    }
                }
            }
        }
        __syncthreads();
    }

#pragma unroll
    for (int mt = 0; mt < 2; mt++) {
        int r0 = blockRow + wm * 32 + mt * 16 + (lane >> 2);
        int r1 = r0 + 8;
#pragma unroll
        for (int nt = 0; nt < 8; nt++) {
            int cb = wn * 64 + nt * 8 + (lane & 3) * 2;
            float2 bb = *reinterpret_cast<const float2*>(bias + cb);
            float2 o0, o1;
            o0.x = acc[mt][nt][0] + bb.x;
            o0.y = acc[mt][nt][1] + bb.y;
            o1.x = acc[mt][nt][2] + bb.x;
            o1.y = acc[mt][nt][3] + bb.y;
            *reinterpret_cast<float2*>(out + (size_t)r0 * 128 + cb) = o0;
            *reinterpret_cast<float2*>(out + (size_t)r1 * 128 + cb) = o1;
        }
    }
}

// ---------------------------------------------------------------------------
extern "C" void kernel_launch(void* const* d_in, const int* in_sizes, int n_in,
                              void* d_out, int out_size) {
    const float* ndata = (const float*)d_in[0];
    const int*   src   = (const int*)d_in[1];
    const int*   dst   = (const int*)d_in[2];
    const float* W     = (const float*)d_in[3];
    const float* b     = (const float*)d_in[4];
    float* out = (float*)d_out;

    (void)in_sizes; (void)n_in; (void)out_size;

    cudaFuncSetAttribute(k_gemm_mma, cudaFuncAttributeMaxDynamicSharedMemorySize,
                         SMEM_GEMM);

    k_head<<<(N_NODES * DFEAT / 4 + 255) / 256, 256>>>(ndata, W, dst);
    k_scan<<<SCAN_BLOCKS, 1024>>>();
    k_fill<<<(N_EDGES / 8 + 255) / 256, 256>>>(src, dst);
    {
        long long threads = (long long)N_NODES * 32;
        int blocks = (int)((threads + 255) / 256);
        k_gather<<<blocks, 256>>>(ndata);
    }
    k_gemm_mma<<<250, 320, SMEM_GEMM>>>(b, out);
}